// round 1
// baseline (speedup 1.0000x reference)
#include <cuda_runtime.h>
#include <math.h>

#define BB 2
#define SS 2048
#define DM 1024
#define NH 16
#define HD 64
#define MT (BB*SS)   // 4096 rows total

// Scratch (allocation-free): Q/K/V in [B,H,S,D], ctx in [B,S,H*D]
__device__ float g_q[BB*NH*SS*HD];
__device__ float g_k[BB*NH*SS*HD];
__device__ float g_v[BB*NH*SS*HD];
__device__ float g_ctx[MT*DM];

// ---------------------------------------------------------------------------
// Tiled SGEMM: C = tanh(A @ W + bias). 128x128 block tile, K-step 8,
// 256 threads, 8x8 register microtile per thread.
// MODE 0: A=[4096,1024] states, blockIdx.z selects (Wq,bq)->g_q etc,
//         output scattered into [B,H,S,D].
// MODE 1: A=g_ctx, W=Wo, bias=bo, plain row-major write to out.
// ---------------------------------------------------------------------------
template<int MODE>
__global__ void __launch_bounds__(256) gemm_bias_tanh(
    const float* __restrict__ A,
    const float* __restrict__ Wq, const float* __restrict__ bq,
    const float* __restrict__ Wk, const float* __restrict__ bk,
    const float* __restrict__ Wv, const float* __restrict__ bv,
    float* __restrict__ outO)
{
    __shared__ float As[8 * 128];   // transposed: As[k][m]
    __shared__ float Bs[8 * 128];   // Bs[k][n]

    const float* W;
    const float* bias;
    float* outp;
    if (MODE == 0) {
        int z = blockIdx.z;
        W    = (z == 0) ? Wq : (z == 1) ? Wk : Wv;
        bias = (z == 0) ? bq : (z == 1) ? bk : bv;
        outp = (z == 0) ? g_q : (z == 1) ? g_k : g_v;
    } else {
        W = Wq; bias = bq; outp = outO;
    }

    const int tid = threadIdx.x;
    const int bm = blockIdx.y * 128;
    const int bn = blockIdx.x * 128;
    const int ty = tid >> 4;        // 0..15
    const int tx = tid & 15;        // 0..15

    const int arow = tid >> 1;          // 0..127
    const int acol = (tid & 1) * 4;     // 0 or 4
    const int brow = tid >> 5;          // 0..7
    const int bcol = (tid & 31) * 4;    // 0..124

    float acc[8][8];
    #pragma unroll
    for (int i = 0; i < 8; i++)
        #pragma unroll
        for (int j = 0; j < 8; j++) acc[i][j] = 0.f;

    for (int k0 = 0; k0 < DM; k0 += 8) {
        float4 av = *(const float4*)&A[(size_t)(bm + arow) * DM + k0 + acol];
        As[(acol + 0) * 128 + arow] = av.x;
        As[(acol + 1) * 128 + arow] = av.y;
        As[(acol + 2) * 128 + arow] = av.z;
        As[(acol + 3) * 128 + arow] = av.w;
        *(float4*)&Bs[brow * 128 + bcol] =
            *(const float4*)&W[(size_t)(k0 + brow) * DM + bn + bcol];
        __syncthreads();

        #pragma unroll
        for (int kk = 0; kk < 8; kk++) {
            float a[8], b[8];
            *(float4*)&a[0] = *(float4*)&As[kk * 128 + ty * 8];
            *(float4*)&a[4] = *(float4*)&As[kk * 128 + ty * 8 + 4];
            *(float4*)&b[0] = *(float4*)&Bs[kk * 128 + tx * 8];
            *(float4*)&b[4] = *(float4*)&Bs[kk * 128 + tx * 8 + 4];
            #pragma unroll
            for (int i = 0; i < 8; i++)
                #pragma unroll
                for (int j = 0; j < 8; j++)
                    acc[i][j] += a[i] * b[j];
        }
        __syncthreads();
    }

    #pragma unroll
    for (int i = 0; i < 8; i++) {
        int m = bm + ty * 8 + i;
        #pragma unroll
        for (int j = 0; j < 8; j++) {
            int n = bn + tx * 8 + j;
            float y = tanhf(acc[i][j] + bias[n]);
            if (MODE == 0) {
                int bb = m >> 11;        // m / 2048
                int s  = m & 2047;
                int h  = n >> 6;         // n / 64
                int d  = n & 63;
                outp[(((size_t)bb * NH + h) * SS + s) * HD + d] = y;
            } else {
                outp[(size_t)m * DM + n] = y;
            }
        }
    }
}

// ---------------------------------------------------------------------------
// Causal flash attention, fp32. One CTA per (b, h, 64-row q tile).
// 256 threads as 16x16; each thread owns a 4x4 tile of (q-rows x k-cols)
// for scores and a 4x4 tile of (q-rows x d-cols) for the output accumulator.
// K stored transposed in smem (row stride 68 keeps float4 alignment and
// conflict-free reads). Online softmax; shfl reductions across tx lanes.
// ---------------------------------------------------------------------------
#define KT_STRIDE 68
#define SMEM_ATTN ((4096 + 64*KT_STRIDE + 4096 + 4096) * 4)

__global__ void __launch_bounds__(256) flash_attn_kernel()
{
    extern __shared__ float sm[];
    float* Qs = sm;                       // [64][64]
    float* Kt = sm + 4096;                // [64][68] transposed: Kt[d][c]
    float* Vs = sm + 4096 + 64 * KT_STRIDE; // [64][64]
    float* Ps = Vs + 4096;                // [64][64]

    const int tid = threadIdx.x;
    const int qt = blockIdx.x;            // 0..31
    const int h  = blockIdx.y;            // 0..15
    const int b  = blockIdx.z;            // 0..1
    const int ty = tid >> 4;
    const int tx = tid & 15;
    const int q0 = qt * 64;

    const size_t head_off = ((size_t)(b * NH + h)) * SS * HD;
    const float* Qg = g_q + head_off;
    const float* Kg = g_k + head_off;
    const float* Vg = g_v + head_off;

    // Load Q tile (64x64): 1024 float4s over 256 threads
    for (int i = tid; i < 1024; i += 256) {
        int r = i >> 4, c4 = (i & 15) * 4;
        *(float4*)&Qs[r * 64 + c4] = *(const float4*)&Qg[(size_t)(q0 + r) * HD + c4];
    }

    float m_i[4], l_i[4], o[4][4];
    #pragma unroll
    for (int i = 0; i < 4; i++) {
        m_i[i] = -1e30f; l_i[i] = 0.f;
        #pragma unroll
        for (int j = 0; j < 4; j++) o[i][j] = 0.f;
    }

    for (int kt = 0; kt <= qt; kt++) {
        const int k0 = kt * 64;
        // Load K (transposed) and V tile
        for (int i = tid; i < 1024; i += 256) {
            int r = i >> 4, c4 = (i & 15) * 4;
            float4 kv = *(const float4*)&Kg[(size_t)(k0 + r) * HD + c4];
            Kt[(c4 + 0) * KT_STRIDE + r] = kv.x;
            Kt[(c4 + 1) * KT_STRIDE + r] = kv.y;
            Kt[(c4 + 2) * KT_STRIDE + r] = kv.z;
            Kt[(c4 + 3) * KT_STRIDE + r] = kv.w;
            *(float4*)&Vs[r * 64 + c4] = *(const float4*)&Vg[(size_t)(k0 + r) * HD + c4];
        }
        __syncthreads();

        // Scores: sc[i][j] = sum_d Q[ty*4+i][d] * K[tx*4+j][d]
        float sc[4][4];
        #pragma unroll
        for (int i = 0; i < 4; i++)
            #pragma unroll
            for (int j = 0; j < 4; j++) sc[i][j] = 0.f;

        #pragma unroll
        for (int d = 0; d < 64; d += 4) {
            float qa[4][4];   // [i][dd]
            #pragma unroll
            for (int i = 0; i < 4; i++) {
                float4 t = *(float4*)&Qs[(ty * 4 + i) * 64 + d];
                qa[i][0] = t.x; qa[i][1] = t.y; qa[i][2] = t.z; qa[i][3] = t.w;
            }
            float ka[4][4];   // [dd][j]
            #pragma unroll
            for (int dd = 0; dd < 4; dd++) {
                float4 t = *(float4*)&Kt[(d + dd) * KT_STRIDE + tx * 4];
                ka[dd][0] = t.x; ka[dd][1] = t.y; ka[dd][2] = t.z; ka[dd][3] = t.w;
            }
            #pragma unroll
            for (int i = 0; i < 4; i++)
                #pragma unroll
                for (int dd = 0; dd < 4; dd++)
                    #pragma unroll
                    for (int j = 0; j < 4; j++)
                        sc[i][j] += qa[i][dd] * ka[dd][j];
        }

        const bool diag = (kt == qt);
        #pragma unroll
        for (int i = 0; i < 4; i++) {
            float rowm = -1e30f;
            #pragma unroll
            for (int j = 0; j < 4; j++) {
                float s = sc[i][j] * 0.125f;    // 1/sqrt(64)
                if (diag && (tx * 4 + j) > (ty * 4 + i)) s = -1e30f;
                sc[i][j] = s;
                rowm = fmaxf(rowm, s);
            }
            #pragma unroll
            for (int off = 8; off > 0; off >>= 1)
                rowm = fmaxf(rowm, __shfl_xor_sync(0xffffffffu, rowm, off));
            float mn = fmaxf(m_i[i], rowm);
            float rs = 0.f;
            #pragma unroll
            for (int j = 0; j < 4; j++) {
                float p = __expf(sc[i][j] - mn);
                sc[i][j] = p;
                rs += p;
            }
            #pragma unroll
            for (int off = 8; off > 0; off >>= 1)
                rs += __shfl_xor_sync(0xffffffffu, rs, off);
            float alpha = __expf(m_i[i] - mn);
            l_i[i] = l_i[i] * alpha + rs;
            m_i[i] = mn;
            #pragma unroll
            for (int j = 0; j < 4; j++) o[i][j] *= alpha;
            *(float4*)&Ps[(ty * 4 + i) * 64 + tx * 4] =
                make_float4(sc[i][0], sc[i][1], sc[i][2], sc[i][3]);
        }
        __syncthreads();

        // O += P @ V : o[i][d] += P[ty*4+i][j] * V[j][tx*4+d]
        #pragma unroll
        for (int j0 = 0; j0 < 64; j0 += 4) {
            float pa[4][4];   // [i][jj]
            #pragma unroll
            for (int i = 0; i < 4; i++) {
                float4 t = *(float4*)&Ps[(ty * 4 + i) * 64 + j0];
                pa[i][0] = t.x; pa[i][1] = t.y; pa[i][2] = t.z; pa[i][3] = t.w;
            }
            float va[4][4];   // [jj][d]
            #pragma unroll
            for (int jj = 0; jj < 4; jj++) {
                float4 t = *(float4*)&Vs[(j0 + jj) * 64 + tx * 4];
                va[jj][0] = t.x; va[jj][1] = t.y; va[jj][2] = t.z; va[jj][3] = t.w;
            }
            #pragma unroll
            for (int i = 0; i < 4; i++)
                #pragma unroll
                for (int jj = 0; jj < 4; jj++)
                    #pragma unroll
                    for (int d = 0; d < 4; d++)
                        o[i][d] += pa[i][jj] * va[jj][d];
        }
        __syncthreads();
    }

    // Write ctx in [B, S, H*D] so the output GEMM reads row-major
    #pragma unroll
    for (int i = 0; i < 4; i++) {
        float inv = 1.f / l_i[i];
        int s = q0 + ty * 4 + i;
        float4 ov = make_float4(o[i][0] * inv, o[i][1] * inv,
                                o[i][2] * inv, o[i][3] * inv);
        *(float4*)&g_ctx[((size_t)b * SS + s) * DM + h * HD + tx * 4] = ov;
    }
}

// ---------------------------------------------------------------------------
extern "C" void kernel_launch(void* const* d_in, const int* in_sizes, int n_in,
                              void* d_out, int out_size)
{
    const float* states = (const float*)d_in[0];
    const float* Wq = (const float*)d_in[1];
    const float* bq = (const float*)d_in[2];
    const float* Wk = (const float*)d_in[3];
    const float* bk = (const float*)d_in[4];
    const float* Wv = (const float*)d_in[5];
    const float* bv = (const float*)d_in[6];
    const float* Wo = (const float*)d_in[7];
    const float* bo = (const float*)d_in[8];
    float* out = (float*)d_out;

    float* ctx_ptr = nullptr;
    cudaGetSymbolAddress((void**)&ctx_ptr, g_ctx);
    cudaFuncSetAttribute(flash_attn_kernel,
                         cudaFuncAttributeMaxDynamicSharedMemorySize, SMEM_ATTN);

    // 1) QKV projections (fused over z)
    dim3 gq(DM / 128, MT / 128, 3);
    gemm_bias_tanh<0><<<gq, 256>>>(states, Wq, bq, Wk, bk, Wv, bv, nullptr);

    // 2) causal flash attention
    dim3 ga(SS / 64, NH, BB);
    flash_attn_kernel<<<ga, 256, SMEM_ATTN>>>();

    // 3) output projection
    dim3 go(DM / 128, MT / 128, 1);
    gemm_bias_tanh<1><<<go, 256>>>(ctx_ptr, Wo, bo, Wo, bo, Wo, bo, out);
}

// round 4
// speedup vs baseline: 2.4804x; 2.4804x over previous
#include <cuda_runtime.h>
#include <math.h>
#include <stdint.h>

#define BB 2
#define SS 2048
#define DM 1024
#define NH 16
#define HD 64
#define MT (BB*SS)   // 4096 rows total

// Scratch (allocation-free): Q/K/V in [B,H,S,D], ctx in [B,S,H*D]
__device__ float g_q[BB*NH*SS*HD];
__device__ float g_k[BB*NH*SS*HD];
__device__ float g_v[BB*NH*SS*HD];
__device__ float g_ctx[MT*DM];

__device__ __forceinline__ uint32_t f2tf32(float f) {
    uint32_t r;
    asm("cvt.rna.tf32.f32 %0, %1;" : "=r"(r) : "f"(f));
    return r;
}

__device__ __forceinline__ void mma_tf32(float* c, const uint32_t* a,
                                         uint32_t b0, uint32_t b1) {
    asm volatile(
        "mma.sync.aligned.m16n8k8.row.col.f32.tf32.tf32.f32 "
        "{%0,%1,%2,%3},{%4,%5,%6,%7},{%8,%9},{%0,%1,%2,%3};\n"
        : "+f"(c[0]), "+f"(c[1]), "+f"(c[2]), "+f"(c[3])
        : "r"(a[0]), "r"(a[1]), "r"(a[2]), "r"(a[3]), "r"(b0), "r"(b1));
}

// ---------------------------------------------------------------------------
// TF32 tensor-core GEMM: C = tanh(A @ W + bias).
// CTA tile 128x128, K-step 16, 256 threads = 8 warps (2 x 4), warp tile 64x32.
// ---------------------------------------------------------------------------
#define AS_STRIDE 20
#define BS_STRIDE 136

template<int MODE>
__global__ void __launch_bounds__(256, 2) gemm_tf32_bias_tanh(
    const float* __restrict__ A,
    const float* __restrict__ Wq, const float* __restrict__ bq,
    const float* __restrict__ Wk, const float* __restrict__ bk,
    const float* __restrict__ Wv, const float* __restrict__ bv,
    float* __restrict__ outO)
{
    __shared__ uint32_t As[128 * AS_STRIDE];   // [m][k], k in 0..15
    __shared__ uint32_t Bs[16 * BS_STRIDE];    // [k][n], n in 0..127

    const float* W;
    const float* bias;
    float* outp;
    if (MODE == 0) {
        int z = blockIdx.z;
        W    = (z == 0) ? Wq : (z == 1) ? Wk : Wv;
        bias = (z == 0) ? bq : (z == 1) ? bk : bv;
        outp = (z == 0) ? g_q : (z == 1) ? g_k : g_v;
    } else {
        W = Wq; bias = bq; outp = outO;
    }

    const int tid  = threadIdx.x;
    const int wid  = tid >> 5;
    const int lane = tid & 31;
    const int grp  = lane >> 2;       // 0..7
    const int q    = lane & 3;        // 0..3
    const int wm   = wid & 1;
    const int wn   = wid >> 1;

    const int bm = blockIdx.y * 128;
    const int bn = blockIdx.x * 128;

    const int a_row = tid >> 1;
    const int a_col = (tid & 1) * 8;
    const int b_row = tid >> 5;
    const int b_col = (tid & 31) * 4;

    float acc[4][4][4];
    #pragma unroll
    for (int i = 0; i < 4; i++)
        #pragma unroll
        for (int j = 0; j < 4; j++)
            #pragma unroll
            for (int r = 0; r < 4; r++) acc[i][j][r] = 0.f;

    float4 ra0 = *(const float4*)&A[(size_t)(bm + a_row) * DM + 0 + a_col];
    float4 ra1 = *(const float4*)&A[(size_t)(bm + a_row) * DM + 0 + a_col + 4];
    float4 rb0 = *(const float4*)&W[(size_t)(0 + b_row) * DM + bn + b_col];
    float4 rb1 = *(const float4*)&W[(size_t)(0 + b_row + 8) * DM + bn + b_col];

    for (int k0 = 0; k0 < DM; k0 += 16) {
        {
            uint32_t* pa = &As[a_row * AS_STRIDE + a_col];
            pa[0] = f2tf32(ra0.x); pa[1] = f2tf32(ra0.y);
            pa[2] = f2tf32(ra0.z); pa[3] = f2tf32(ra0.w);
            pa[4] = f2tf32(ra1.x); pa[5] = f2tf32(ra1.y);
            pa[6] = f2tf32(ra1.z); pa[7] = f2tf32(ra1.w);
            uint32_t* pb0 = &Bs[b_row * BS_STRIDE + b_col];
            pb0[0] = f2tf32(rb0.x); pb0[1] = f2tf32(rb0.y);
            pb0[2] = f2tf32(rb0.z); pb0[3] = f2tf32(rb0.w);
            uint32_t* pb1 = &Bs[(b_row + 8) * BS_STRIDE + b_col];
            pb1[0] = f2tf32(rb1.x); pb1[1] = f2tf32(rb1.y);
            pb1[2] = f2tf32(rb1.z); pb1[3] = f2tf32(rb1.w);
        }
        __syncthreads();

        if (k0 + 16 < DM) {
            int kn = k0 + 16;
            ra0 = *(const float4*)&A[(size_t)(bm + a_row) * DM + kn + a_col];
            ra1 = *(const float4*)&A[(size_t)(bm + a_row) * DM + kn + a_col + 4];
            rb0 = *(const float4*)&W[(size_t)(kn + b_row) * DM + bn + b_col];
            rb1 = *(const float4*)&W[(size_t)(kn + b_row + 8) * DM + bn + b_col];
        }

        #pragma unroll
        for (int kk = 0; kk < 16; kk += 8) {
            uint32_t af[4][4];
            #pragma unroll
            for (int im = 0; im < 4; im++) {
                int mb = wm * 64 + im * 16;
                af[im][0] = As[(mb + grp    ) * AS_STRIDE + kk + q];
                af[im][1] = As[(mb + grp + 8) * AS_STRIDE + kk + q];
                af[im][2] = As[(mb + grp    ) * AS_STRIDE + kk + q + 4];
                af[im][3] = As[(mb + grp + 8) * AS_STRIDE + kk + q + 4];
            }
            uint32_t bf[4][2];
            #pragma unroll
            for (int in_ = 0; in_ < 4; in_++) {
                int nb = wn * 32 + in_ * 8;
                bf[in_][0] = Bs[(kk + q    ) * BS_STRIDE + nb + grp];
                bf[in_][1] = Bs[(kk + q + 4) * BS_STRIDE + nb + grp];
            }
            #pragma unroll
            for (int im = 0; im < 4; im++)
                #pragma unroll
                for (int in_ = 0; in_ < 4; in_++)
                    mma_tf32(acc[im][in_], af[im], bf[in_][0], bf[in_][1]);
        }
        __syncthreads();
    }

    #pragma unroll
    for (int im = 0; im < 4; im++) {
        #pragma unroll
        for (int in_ = 0; in_ < 4; in_++) {
            int n0 = bn + wn * 32 + in_ * 8 + 2 * q;
            float b0v = bias[n0], b1v = bias[n0 + 1];
            #pragma unroll
            for (int half = 0; half < 2; half++) {
                int m = bm + wm * 64 + im * 16 + grp + half * 8;
                float y0 = tanhf(acc[im][in_][half * 2 + 0] + b0v);
                float y1 = tanhf(acc[im][in_][half * 2 + 1] + b1v);
                if (MODE == 0) {
                    int bbi = m >> 11;
                    int s   = m & 2047;
                    int h0  = n0 >> 6;
                    int d0  = n0 & 63;
                    size_t base = (((size_t)bbi * NH + h0) * SS + s) * HD + d0;
                    outp[base]     = y0;
                    outp[base + 1] = y1;
                } else {
                    outp[(size_t)m * DM + n0]     = y0;
                    outp[(size_t)m * DM + n0 + 1] = y1;
                }
            }
        }
    }
}

// ---------------------------------------------------------------------------
// TF32 tensor-core causal flash attention.
// CTA = (b, h, 128-row q tile). 8 warps, warp owns 16 q-rows.
// K tiles of 64. S=Q@K^T: mma row.col with K natural layout as B operand.
// Smem strides: Qs/Ks/Ps=68 (conflict-free A/B frag loads), Vs=72.
// P staged per-warp through smem (only __syncwarp needed).
// ---------------------------------------------------------------------------
#define QS_STR 68
#define KS_STR 68
#define VS_STR 72
#define PS_STR 68
#define SMEM_ATTN2 ((128*QS_STR + 64*KS_STR + 64*VS_STR + 128*PS_STR) * 4)

__global__ void __launch_bounds__(256, 1) flash_attn_tf32()
{
    extern __shared__ uint32_t smu[];
    uint32_t* Qs = smu;                      // [128][68]
    uint32_t* Ks = Qs + 128 * QS_STR;        // [64][68]  (row=kseq, col=d)
    uint32_t* Vs = Ks + 64 * KS_STR;         // [64][72]  (row=kseq, col=d)
    uint32_t* Ps = Vs + 64 * VS_STR;         // [128][68]

    const int tid  = threadIdx.x;
    const int wid  = tid >> 5;
    const int lane = tid & 31;
    const int grp  = lane >> 2;
    const int qq   = lane & 3;
    const int qt   = (gridDim.x - 1) - blockIdx.x;   // heavy tiles first
    const int h    = blockIdx.y;
    const int b    = blockIdx.z;
    const int q0   = qt * 128;
    const int mb   = wid * 16;

    const size_t head_off = ((size_t)(b * NH + h)) * SS * HD;
    const float* Qg = g_q + head_off;
    const float* Kg = g_k + head_off;
    const float* Vg = g_v + head_off;

    // Load Q tile (128x64) as tf32
    for (int i = tid; i < 2048; i += 256) {
        int r = i >> 4, c4 = (i & 15) * 4;
        float4 t = *(const float4*)&Qg[(size_t)(q0 + r) * HD + c4];
        uint32_t* p = &Qs[r * QS_STR + c4];
        p[0] = f2tf32(t.x); p[1] = f2tf32(t.y);
        p[2] = f2tf32(t.z); p[3] = f2tf32(t.w);
    }

    float m0 = -1e30f, m1 = -1e30f, l0 = 0.f, l1 = 0.f;
    float o[8][4];
    #pragma unroll
    for (int nf = 0; nf < 8; nf++)
        #pragma unroll
        for (int r = 0; r < 4; r++) o[nf][r] = 0.f;

    const int n_kt = 2 * qt + 2;
    const int row0 = q0 + mb + grp;
    const int row1 = row0 + 8;

    for (int kt = 0; kt < n_kt; kt++) {
        const int k0 = kt * 64;
        __syncthreads();   // previous iteration's K/V reads done
        for (int i = tid; i < 1024; i += 256) {
            int r = i >> 4, c4 = (i & 15) * 4;
            float4 kv = *(const float4*)&Kg[(size_t)(k0 + r) * HD + c4];
            uint32_t* pk = &Ks[r * KS_STR + c4];
            pk[0] = f2tf32(kv.x); pk[1] = f2tf32(kv.y);
            pk[2] = f2tf32(kv.z); pk[3] = f2tf32(kv.w);
            float4 vv = *(const float4*)&Vg[(size_t)(k0 + r) * HD + c4];
            uint32_t* pv = &Vs[r * VS_STR + c4];
            pv[0] = f2tf32(vv.x); pv[1] = f2tf32(vv.y);
            pv[2] = f2tf32(vv.z); pv[3] = f2tf32(vv.w);
        }
        __syncthreads();

        // Warp fully above the diagonal in this tile -> nothing to do
        if (k0 > q0 + mb + 15) continue;

        // S = Q @ K^T  (per-warp 16 x 64)
        float sc[8][4];
        #pragma unroll
        for (int nf = 0; nf < 8; nf++)
            #pragma unroll
            for (int r = 0; r < 4; r++) sc[nf][r] = 0.f;

        #pragma unroll
        for (int kf = 0; kf < 8; kf++) {
            uint32_t a[4];
            a[0] = Qs[(mb + grp    ) * QS_STR + kf * 8 + qq];
            a[1] = Qs[(mb + grp + 8) * QS_STR + kf * 8 + qq];
            a[2] = Qs[(mb + grp    ) * QS_STR + kf * 8 + qq + 4];
            a[3] = Qs[(mb + grp + 8) * QS_STR + kf * 8 + qq + 4];
            #pragma unroll
            for (int nf = 0; nf < 8; nf++) {
                uint32_t b0 = Ks[(nf * 8 + grp) * KS_STR + kf * 8 + qq];
                uint32_t b1 = Ks[(nf * 8 + grp) * KS_STR + kf * 8 + qq + 4];
                mma_tf32(sc[nf], a, b0, b1);
            }
        }

        // scale + causal mask + row max
        const bool diag = (kt >= 2 * qt);   // only last two tiles cross diagonal
        float rm0 = -1e30f, rm1 = -1e30f;
        #pragma unroll
        for (int nf = 0; nf < 8; nf++) {
            int c0 = k0 + nf * 8 + 2 * qq;
            float s0v = sc[nf][0] * 0.125f;
            float s1v = sc[nf][1] * 0.125f;
            float s2v = sc[nf][2] * 0.125f;
            float s3v = sc[nf][3] * 0.125f;
            if (diag) {
                if (c0     > row0) s0v = -1e30f;
                if (c0 + 1 > row0) s1v = -1e30f;
                if (c0     > row1) s2v = -1e30f;
                if (c0 + 1 > row1) s3v = -1e30f;
            }
            sc[nf][0] = s0v; sc[nf][1] = s1v; sc[nf][2] = s2v; sc[nf][3] = s3v;
            rm0 = fmaxf(rm0, fmaxf(s0v, s1v));
            rm1 = fmaxf(rm1, fmaxf(s2v, s3v));
        }
        #pragma unroll
        for (int off = 1; off <= 2; off <<= 1) {
            rm0 = fmaxf(rm0, __shfl_xor_sync(0xffffffffu, rm0, off));
            rm1 = fmaxf(rm1, __shfl_xor_sync(0xffffffffu, rm1, off));
        }
        float mn0 = fmaxf(m0, rm0);
        float mn1 = fmaxf(m1, rm1);

        // exp + row sum + stage P to smem (tf32)
        float s0 = 0.f, s1 = 0.f;
        #pragma unroll
        for (int nf = 0; nf < 8; nf++) {
            float p0 = __expf(sc[nf][0] - mn0);
            float p1 = __expf(sc[nf][1] - mn0);
            float p2 = __expf(sc[nf][2] - mn1);
            float p3 = __expf(sc[nf][3] - mn1);
            s0 += p0 + p1;
            s1 += p2 + p3;
            uint2 u01 = make_uint2(f2tf32(p0), f2tf32(p1));
            uint2 u23 = make_uint2(f2tf32(p2), f2tf32(p3));
            *(uint2*)&Ps[(mb + grp    ) * PS_STR + nf * 8 + 2 * qq] = u01;
            *(uint2*)&Ps[(mb + grp + 8) * PS_STR + nf * 8 + 2 * qq] = u23;
        }
        #pragma unroll
        for (int off = 1; off <= 2; off <<= 1) {
            s0 += __shfl_xor_sync(0xffffffffu, s0, off);
            s1 += __shfl_xor_sync(0xffffffffu, s1, off);
        }
        float a0 = __expf(m0 - mn0);
        float a1 = __expf(m1 - mn1);
        l0 = l0 * a0 + s0;
        l1 = l1 * a1 + s1;
        m0 = mn0; m1 = mn1;
        #pragma unroll
        for (int nf = 0; nf < 8; nf++) {
            o[nf][0] *= a0; o[nf][1] *= a0;
            o[nf][2] *= a1; o[nf][3] *= a1;
        }
        __syncwarp();

        // O += P @ V  (per-warp 16 x 64, k = 64 seq)
        #pragma unroll
        for (int kf = 0; kf < 8; kf++) {
            uint32_t a[4];
            a[0] = Ps[(mb + grp    ) * PS_STR + kf * 8 + qq];
            a[1] = Ps[(mb + grp + 8) * PS_STR + kf * 8 + qq];
            a[2] = Ps[(mb + grp    ) * PS_STR + kf * 8 + qq + 4];
            a[3] = Ps[(mb + grp + 8) * PS_STR + kf * 8 + qq + 4];
            #pragma unroll
            for (int nf = 0; nf < 8; nf++) {
                uint32_t b0 = Vs[(kf * 8 + qq    ) * VS_STR + nf * 8 + grp];
                uint32_t b1 = Vs[(kf * 8 + qq + 4) * VS_STR + nf * 8 + grp];
                mma_tf32(o[nf], a, b0, b1);
            }
        }
    }

    // finalize + write ctx [B, S, H*D]
    float inv0 = 1.f / l0;
    float inv1 = 1.f / l1;
    #pragma unroll
    for (int nf = 0; nf < 8; nf++) {
        int c = h * HD + nf * 8 + 2 * qq;
        *(float2*)&g_ctx[((size_t)b * SS + row0) * DM + c] =
            make_float2(o[nf][0] * inv0, o[nf][1] * inv0);
        *(float2*)&g_ctx[((size_t)b * SS + row1) * DM + c] =
            make_float2(o[nf][2] * inv1, o[nf][3] * inv1);
    }
}

// ---------------------------------------------------------------------------
extern "C" void kernel_launch(void* const* d_in, const int* in_sizes, int n_in,
                              void* d_out, int out_size)
{
    const float* states = (const float*)d_in[0];
    const float* Wq = (const float*)d_in[1];
    const float* bq = (const float*)d_in[2];
    const float* Wk = (const float*)d_in[3];
    const float* bk = (const float*)d_in[4];
    const float* Wv = (const float*)d_in[5];
    const float* bv = (const float*)d_in[6];
    const float* Wo = (const float*)d_in[7];
    const float* bo = (const float*)d_in[8];
    float* out = (float*)d_out;

    float* ctx_ptr = nullptr;
    cudaGetSymbolAddress((void**)&ctx_ptr, g_ctx);
    cudaFuncSetAttribute(flash_attn_tf32,
                         cudaFuncAttributeMaxDynamicSharedMemorySize, SMEM_ATTN2);

    // 1) QKV projections (fused over z), tensor-core TF32
    dim3 gq(DM / 128, MT / 128, 3);
    gemm_tf32_bias_tanh<0><<<gq, 256>>>(states, Wq, bq, Wk, bk, Wv, bv, nullptr);

    // 2) causal flash attention, tensor-core TF32
    dim3 ga(SS / 128, NH, BB);
    flash_attn_tf32<<<ga, 256, SMEM_ATTN2>>>();

    // 3) output projection
    dim3 go(DM / 128, MT / 128, 1);
    gemm_tf32_bias_tanh<1><<<go, 256>>>(ctx_ptr, Wo, bo, Wo, bo, Wo, bo, out);
}

// round 5
// speedup vs baseline: 2.5876x; 1.0432x over previous
#include <cuda_runtime.h>
#include <math.h>
#include <stdint.h>

#define BB 2
#define SS 2048
#define DM 1024
#define NH 16
#define HD 64
#define MT (BB*SS)   // 4096 rows total

// Scratch (allocation-free): Q/K/V in [B,H,S,D], ctx in [B,S,H*D]
__device__ float g_q[BB*NH*SS*HD];
__device__ float g_k[BB*NH*SS*HD];
__device__ float g_v[BB*NH*SS*HD];
__device__ float g_ctx[MT*DM];

__device__ __forceinline__ uint32_t f2tf32(float f) {
    uint32_t r;
    asm("cvt.rna.tf32.f32 %0, %1;" : "=r"(r) : "f"(f));
    return r;
}

__device__ __forceinline__ void mma_tf32(float* c, const uint32_t* a,
                                         uint32_t b0, uint32_t b1) {
    asm volatile(
        "mma.sync.aligned.m16n8k8.row.col.f32.tf32.tf32.f32 "
        "{%0,%1,%2,%3},{%4,%5,%6,%7},{%8,%9},{%0,%1,%2,%3};\n"
        : "+f"(c[0]), "+f"(c[1]), "+f"(c[2]), "+f"(c[3])
        : "r"(a[0]), "r"(a[1]), "r"(a[2]), "r"(a[3]), "r"(b0), "r"(b1));
}

// ---------------------------------------------------------------------------
// TF32 tensor-core GEMM: C = tanh(A @ W + bias).
// CTA tile 128x128, K-step 16, 256 threads = 8 warps (2 x 4), warp tile 64x32.
// Double-buffered smem: one __syncthreads per K-iter; MMAs on buffer `cur`
// overlap the global loads for buffer `1-cur`.
// ---------------------------------------------------------------------------
#define AS_STRIDE 20
#define BS_STRIDE 136

template<int MODE>
__global__ void __launch_bounds__(256, 2) gemm_tf32_bias_tanh(
    const float* __restrict__ A,
    const float* __restrict__ Wq, const float* __restrict__ bq,
    const float* __restrict__ Wk, const float* __restrict__ bk,
    const float* __restrict__ Wv, const float* __restrict__ bv,
    float* __restrict__ outO)
{
    __shared__ uint32_t As[2][128 * AS_STRIDE];   // [m][k], k in 0..15
    __shared__ uint32_t Bs[2][16 * BS_STRIDE];    // [k][n], n in 0..127

    const float* W;
    const float* bias;
    float* outp;
    if (MODE == 0) {
        int z = blockIdx.z;
        W    = (z == 0) ? Wq : (z == 1) ? Wk : Wv;
        bias = (z == 0) ? bq : (z == 1) ? bk : bv;
        outp = (z == 0) ? g_q : (z == 1) ? g_k : g_v;
    } else {
        W = Wq; bias = bq; outp = outO;
    }

    const int tid  = threadIdx.x;
    const int wid  = tid >> 5;
    const int lane = tid & 31;
    const int grp  = lane >> 2;       // 0..7
    const int q    = lane & 3;        // 0..3
    const int wm   = wid & 1;
    const int wn   = wid >> 1;

    const int bm = blockIdx.y * 128;
    const int bn = blockIdx.x * 128;

    const int a_row = tid >> 1;
    const int a_col = (tid & 1) * 8;
    const int b_row = tid >> 5;
    const int b_col = (tid & 31) * 4;

    const float* Aptr  = &A[(size_t)(bm + a_row) * DM + a_col];
    const float* Wptr0 = &W[(size_t)b_row * DM + bn + b_col];
    const float* Wptr1 = &W[(size_t)(b_row + 8) * DM + bn + b_col];

    float acc[4][4][4];
    #pragma unroll
    for (int i = 0; i < 4; i++)
        #pragma unroll
        for (int j = 0; j < 4; j++)
            #pragma unroll
            for (int r = 0; r < 4; r++) acc[i][j][r] = 0.f;

    // Prologue: load tile 0, convert, store to buffer 0
    {
        float4 ra0 = *(const float4*)&Aptr[0];
        float4 ra1 = *(const float4*)&Aptr[4];
        float4 rb0 = *(const float4*)&Wptr0[0];
        float4 rb1 = *(const float4*)&Wptr1[0];
        uint4 ua0 = make_uint4(f2tf32(ra0.x), f2tf32(ra0.y), f2tf32(ra0.z), f2tf32(ra0.w));
        uint4 ua1 = make_uint4(f2tf32(ra1.x), f2tf32(ra1.y), f2tf32(ra1.z), f2tf32(ra1.w));
        uint4 ub0 = make_uint4(f2tf32(rb0.x), f2tf32(rb0.y), f2tf32(rb0.z), f2tf32(rb0.w));
        uint4 ub1 = make_uint4(f2tf32(rb1.x), f2tf32(rb1.y), f2tf32(rb1.z), f2tf32(rb1.w));
        *(uint4*)&As[0][a_row * AS_STRIDE + a_col]     = ua0;
        *(uint4*)&As[0][a_row * AS_STRIDE + a_col + 4] = ua1;
        *(uint4*)&Bs[0][b_row * BS_STRIDE + b_col]       = ub0;
        *(uint4*)&Bs[0][(b_row + 8) * BS_STRIDE + b_col] = ub1;
    }
    __syncthreads();

    int cur = 0;
    for (int k0 = 0; k0 < DM; k0 += 16) {
        const bool has_next = (k0 + 16 < DM);
        float4 ra0, ra1, rb0, rb1;
        if (has_next) {
            int kn = k0 + 16;
            ra0 = *(const float4*)&Aptr[kn];
            ra1 = *(const float4*)&Aptr[kn + 4];
            rb0 = *(const float4*)&Wptr0[(size_t)kn * DM];
            rb1 = *(const float4*)&Wptr1[(size_t)kn * DM];
        }

        // MMAs on current buffer (overlaps the in-flight global loads)
        const uint32_t* Ac = As[cur];
        const uint32_t* Bc = Bs[cur];
        #pragma unroll
        for (int kk = 0; kk < 16; kk += 8) {
            uint32_t af[4][4];
            #pragma unroll
            for (int im = 0; im < 4; im++) {
                int mb = wm * 64 + im * 16;
                af[im][0] = Ac[(mb + grp    ) * AS_STRIDE + kk + q];
                af[im][1] = Ac[(mb + grp + 8) * AS_STRIDE + kk + q];
                af[im][2] = Ac[(mb + grp    ) * AS_STRIDE + kk + q + 4];
                af[im][3] = Ac[(mb + grp + 8) * AS_STRIDE + kk + q + 4];
            }
            uint32_t bf[4][2];
            #pragma unroll
            for (int in_ = 0; in_ < 4; in_++) {
                int nb = wn * 32 + in_ * 8;
                bf[in_][0] = Bc[(kk + q    ) * BS_STRIDE + nb + grp];
                bf[in_][1] = Bc[(kk + q + 4) * BS_STRIDE + nb + grp];
            }
            #pragma unroll
            for (int im = 0; im < 4; im++)
                #pragma unroll
                for (int in_ = 0; in_ < 4; in_++)
                    mma_tf32(acc[im][in_], af[im], bf[in_][0], bf[in_][1]);
        }

        // Store next tile into the other buffer
        if (has_next) {
            int nxt = cur ^ 1;
            uint4 ua0 = make_uint4(f2tf32(ra0.x), f2tf32(ra0.y), f2tf32(ra0.z), f2tf32(ra0.w));
            uint4 ua1 = make_uint4(f2tf32(ra1.x), f2tf32(ra1.y), f2tf32(ra1.z), f2tf32(ra1.w));
            uint4 ub0 = make_uint4(f2tf32(rb0.x), f2tf32(rb0.y), f2tf32(rb0.z), f2tf32(rb0.w));
            uint4 ub1 = make_uint4(f2tf32(rb1.x), f2tf32(rb1.y), f2tf32(rb1.z), f2tf32(rb1.w));
            *(uint4*)&As[nxt][a_row * AS_STRIDE + a_col]     = ua0;
            *(uint4*)&As[nxt][a_row * AS_STRIDE + a_col + 4] = ua1;
            *(uint4*)&Bs[nxt][b_row * BS_STRIDE + b_col]       = ub0;
            *(uint4*)&Bs[nxt][(b_row + 8) * BS_STRIDE + b_col] = ub1;
        }
        __syncthreads();
        cur ^= 1;
    }

    #pragma unroll
    for (int im = 0; im < 4; im++) {
        #pragma unroll
        for (int in_ = 0; in_ < 4; in_++) {
            int n0 = bn + wn * 32 + in_ * 8 + 2 * q;
            float b0v = bias[n0], b1v = bias[n0 + 1];
            #pragma unroll
            for (int half = 0; half < 2; half++) {
                int m = bm + wm * 64 + im * 16 + grp + half * 8;
                float y0 = tanhf(acc[im][in_][half * 2 + 0] + b0v);
                float y1 = tanhf(acc[im][in_][half * 2 + 1] + b1v);
                if (MODE == 0) {
                    int bbi = m >> 11;
                    int s   = m & 2047;
                    int h0  = n0 >> 6;
                    int d0  = n0 & 63;
                    size_t base = (((size_t)bbi * NH + h0) * SS + s) * HD + d0;
                    outp[base]     = y0;
                    outp[base + 1] = y1;
                } else {
                    outp[(size_t)m * DM + n0]     = y0;
                    outp[(size_t)m * DM + n0 + 1] = y1;
                }
            }
        }
    }
}

// ---------------------------------------------------------------------------
// TF32 tensor-core causal flash attention. (Same structure as R4; now 2
// CTAs/SM via launch bounds so skewed tiles overlap.)
// ---------------------------------------------------------------------------
#define QS_STR 68
#define KS_STR 68
#define VS_STR 72
#define PS_STR 68
#define SMEM_ATTN2 ((128*QS_STR + 64*KS_STR + 64*VS_STR + 128*PS_STR) * 4)

__global__ void __launch_bounds__(256, 2) flash_attn_tf32()
{
    extern __shared__ uint32_t smu[];
    uint32_t* Qs = smu;                      // [128][68]
    uint32_t* Ks = Qs + 128 * QS_STR;        // [64][68]  (row=kseq, col=d)
    uint32_t* Vs = Ks + 64 * KS_STR;         // [64][72]  (row=kseq, col=d)
    uint32_t* Ps = Vs + 64 * VS_STR;         // [128][68]

    const int tid  = threadIdx.x;
    const int wid  = tid >> 5;
    const int lane = tid & 31;
    const int grp  = lane >> 2;
    const int qq   = lane & 3;
    const int qt   = (gridDim.x - 1) - blockIdx.x;   // heavy tiles first
    const int h    = blockIdx.y;
    const int b    = blockIdx.z;
    const int q0   = qt * 128;
    const int mb   = wid * 16;

    const size_t head_off = ((size_t)(b * NH + h)) * SS * HD;
    const float* Qg = g_q + head_off;
    const float* Kg = g_k + head_off;
    const float* Vg = g_v + head_off;

    for (int i = tid; i < 2048; i += 256) {
        int r = i >> 4, c4 = (i & 15) * 4;
        float4 t = *(const float4*)&Qg[(size_t)(q0 + r) * HD + c4];
        uint32_t* p = &Qs[r * QS_STR + c4];
        p[0] = f2tf32(t.x); p[1] = f2tf32(t.y);
        p[2] = f2tf32(t.z); p[3] = f2tf32(t.w);
    }

    float m0 = -1e30f, m1 = -1e30f, l0 = 0.f, l1 = 0.f;
    float o[8][4];
    #pragma unroll
    for (int nf = 0; nf < 8; nf++)
        #pragma unroll
        for (int r = 0; r < 4; r++) o[nf][r] = 0.f;

    const int n_kt = 2 * qt + 2;
    const int row0 = q0 + mb + grp;
    const int row1 = row0 + 8;

    for (int kt = 0; kt < n_kt; kt++) {
        const int k0 = kt * 64;
        __syncthreads();   // previous iteration's K/V reads done
        for (int i = tid; i < 1024; i += 256) {
            int r = i >> 4, c4 = (i & 15) * 4;
            float4 kv = *(const float4*)&Kg[(size_t)(k0 + r) * HD + c4];
            uint32_t* pk = &Ks[r * KS_STR + c4];
            pk[0] = f2tf32(kv.x); pk[1] = f2tf32(kv.y);
            pk[2] = f2tf32(kv.z); pk[3] = f2tf32(kv.w);
            float4 vv = *(const float4*)&Vg[(size_t)(k0 + r) * HD + c4];
            uint32_t* pv = &Vs[r * VS_STR + c4];
            pv[0] = f2tf32(vv.x); pv[1] = f2tf32(vv.y);
            pv[2] = f2tf32(vv.z); pv[3] = f2tf32(vv.w);
        }
        __syncthreads();

        if (k0 > q0 + mb + 15) continue;

        float sc[8][4];
        #pragma unroll
        for (int nf = 0; nf < 8; nf++)
            #pragma unroll
            for (int r = 0; r < 4; r++) sc[nf][r] = 0.f;

        #pragma unroll
        for (int kf = 0; kf < 8; kf++) {
            uint32_t a[4];
            a[0] = Qs[(mb + grp    ) * QS_STR + kf * 8 + qq];
            a[1] = Qs[(mb + grp + 8) * QS_STR + kf * 8 + qq];
            a[2] = Qs[(mb + grp    ) * QS_STR + kf * 8 + qq + 4];
            a[3] = Qs[(mb + grp + 8) * QS_STR + kf * 8 + qq + 4];
            #pragma unroll
            for (int nf = 0; nf < 8; nf++) {
                uint32_t b0 = Ks[(nf * 8 + grp) * KS_STR + kf * 8 + qq];
                uint32_t b1 = Ks[(nf * 8 + grp) * KS_STR + kf * 8 + qq + 4];
                mma_tf32(sc[nf], a, b0, b1);
            }
        }

        const bool diag = (kt >= 2 * qt);
        float rm0 = -1e30f, rm1 = -1e30f;
        #pragma unroll
        for (int nf = 0; nf < 8; nf++) {
            int c0 = k0 + nf * 8 + 2 * qq;
            float s0v = sc[nf][0] * 0.125f;
            float s1v = sc[nf][1] * 0.125f;
            float s2v = sc[nf][2] * 0.125f;
            float s3v = sc[nf][3] * 0.125f;
            if (diag) {
                if (c0     > row0) s0v = -1e30f;
                if (c0 + 1 > row0) s1v = -1e30f;
                if (c0     > row1) s2v = -1e30f;
                if (c0 + 1 > row1) s3v = -1e30f;
            }
            sc[nf][0] = s0v; sc[nf][1] = s1v; sc[nf][2] = s2v; sc[nf][3] = s3v;
            rm0 = fmaxf(rm0, fmaxf(s0v, s1v));
            rm1 = fmaxf(rm1, fmaxf(s2v, s3v));
        }
        #pragma unroll
        for (int off = 1; off <= 2; off <<= 1) {
            rm0 = fmaxf(rm0, __shfl_xor_sync(0xffffffffu, rm0, off));
            rm1 = fmaxf(rm1, __shfl_xor_sync(0xffffffffu, rm1, off));
        }
        float mn0 = fmaxf(m0, rm0);
        float mn1 = fmaxf(m1, rm1);

        float s0 = 0.f, s1 = 0.f;
        #pragma unroll
        for (int nf = 0; nf < 8; nf++) {
            float p0 = __expf(sc[nf][0] - mn0);
            float p1 = __expf(sc[nf][1] - mn0);
            float p2 = __expf(sc[nf][2] - mn1);
            float p3 = __expf(sc[nf][3] - mn1);
            s0 += p0 + p1;
            s1 += p2 + p3;
            uint2 u01 = make_uint2(f2tf32(p0), f2tf32(p1));
            uint2 u23 = make_uint2(f2tf32(p2), f2tf32(p3));
            *(uint2*)&Ps[(mb + grp    ) * PS_STR + nf * 8 + 2 * qq] = u01;
            *(uint2*)&Ps[(mb + grp + 8) * PS_STR + nf * 8 + 2 * qq] = u23;
        }
        #pragma unroll
        for (int off = 1; off <= 2; off <<= 1) {
            s0 += __shfl_xor_sync(0xffffffffu, s0, off);
            s1 += __shfl_xor_sync(0xffffffffu, s1, off);
        }
        float a0 = __expf(m0 - mn0);
        float a1 = __expf(m1 - mn1);
        l0 = l0 * a0 + s0;
        l1 = l1 * a1 + s1;
        m0 = mn0; m1 = mn1;
        #pragma unroll
        for (int nf = 0; nf < 8; nf++) {
            o[nf][0] *= a0; o[nf][1] *= a0;
            o[nf][2] *= a1; o[nf][3] *= a1;
        }
        __syncwarp();

        #pragma unroll
        for (int kf = 0; kf < 8; kf++) {
            uint32_t a[4];
            a[0] = Ps[(mb + grp    ) * PS_STR + kf * 8 + qq];
            a[1] = Ps[(mb + grp + 8) * PS_STR + kf * 8 + qq];
            a[2] = Ps[(mb + grp    ) * PS_STR + kf * 8 + qq + 4];
            a[3] = Ps[(mb + grp + 8) * PS_STR + kf * 8 + qq + 4];
            #pragma unroll
            for (int nf = 0; nf < 8; nf++) {
                uint32_t b0 = Vs[(kf * 8 + qq    ) * VS_STR + nf * 8 + grp];
                uint32_t b1 = Vs[(kf * 8 + qq + 4) * VS_STR + nf * 8 + grp];
                mma_tf32(o[nf], a, b0, b1);
            }
        }
    }

    float inv0 = 1.f / l0;
    float inv1 = 1.f / l1;
    #pragma unroll
    for (int nf = 0; nf < 8; nf++) {
        int c = h * HD + nf * 8 + 2 * qq;
        *(float2*)&g_ctx[((size_t)b * SS + row0) * DM + c] =
            make_float2(o[nf][0] * inv0, o[nf][1] * inv0);
        *(float2*)&g_ctx[((size_t)b * SS + row1) * DM + c] =
            make_float2(o[nf][2] * inv1, o[nf][3] * inv1);
    }
}

// ---------------------------------------------------------------------------
extern "C" void kernel_launch(void* const* d_in, const int* in_sizes, int n_in,
                              void* d_out, int out_size)
{
    const float* states = (const float*)d_in[0];
    const float* Wq = (const float*)d_in[1];
    const float* bq = (const float*)d_in[2];
    const float* Wk = (const float*)d_in[3];
    const float* bk = (const float*)d_in[4];
    const float* Wv = (const float*)d_in[5];
    const float* bv = (const float*)d_in[6];
    const float* Wo = (const float*)d_in[7];
    const float* bo = (const float*)d_in[8];
    float* out = (float*)d_out;

    float* ctx_ptr = nullptr;
    cudaGetSymbolAddress((void**)&ctx_ptr, g_ctx);
    cudaFuncSetAttribute(flash_attn_tf32,
                         cudaFuncAttributeMaxDynamicSharedMemorySize, SMEM_ATTN2);

    // 1) QKV projections (fused over z), tensor-core TF32
    dim3 gq(DM / 128, MT / 128, 3);
    gemm_tf32_bias_tanh<0><<<gq, 256>>>(states, Wq, bq, Wk, bk, Wv, bv, nullptr);

    // 2) causal flash attention, tensor-core TF32
    dim3 ga(SS / 128, NH, BB);
    flash_attn_tf32<<<ga, 256, SMEM_ATTN2>>>();

    // 3) output projection
    dim3 go(DM / 128, MT / 128, 1);
    gemm_tf32_bias_tanh<1><<<go, 256>>>(ctx_ptr, Wo, bo, Wo, bo, Wo, bo, out);
}

// round 7
// speedup vs baseline: 2.7656x; 1.0688x over previous
#include <cuda_runtime.h>
#include <math.h>
#include <stdint.h>

#define BB 2
#define SS 2048
#define DM 1024
#define NH 16
#define HD 64
#define MT (BB*SS)   // 4096 rows total

// Scratch (allocation-free): Q/K/V in [B,H,S,D], ctx in [B,S,H*D]
__device__ float g_q[BB*NH*SS*HD];
__device__ float g_k[BB*NH*SS*HD];
__device__ float g_v[BB*NH*SS*HD];
__device__ float g_ctx[MT*DM];

__device__ __forceinline__ uint32_t f2tf32(float f) {
    uint32_t r;
    asm("cvt.rna.tf32.f32 %0, %1;" : "=r"(r) : "f"(f));
    return r;
}

__device__ __forceinline__ uint32_t smem_u32(const void* p) {
    uint32_t a;
    asm("{ .reg .u64 t; cvta.to.shared.u64 t, %1; cvt.u32.u64 %0, t; }"
        : "=r"(a) : "l"(p));
    return a;
}

__device__ __forceinline__ void mma_tf32(float* c, const uint32_t* a,
                                         uint32_t b0, uint32_t b1) {
    asm volatile(
        "mma.sync.aligned.m16n8k8.row.col.f32.tf32.tf32.f32 "
        "{%0,%1,%2,%3},{%4,%5,%6,%7},{%8,%9},{%0,%1,%2,%3};\n"
        : "+f"(c[0]), "+f"(c[1]), "+f"(c[2]), "+f"(c[3])
        : "r"(a[0]), "r"(a[1]), "r"(a[2]), "r"(a[3]), "r"(b0), "r"(b1));
}

// ldmatrix x4: 4 8x8-b16 matrices == m16n8k8 tf32 A-frag (or 2 B-frags).
__device__ __forceinline__ void ldsm_x4(uint32_t* r, uint32_t saddr) {
    asm volatile(
        "ldmatrix.sync.aligned.m8n8.x4.shared.b16 {%0,%1,%2,%3}, [%4];"
        : "=r"(r[0]), "=r"(r[1]), "=r"(r[2]), "=r"(r[3])
        : "r"(saddr));
}

// ---------------------------------------------------------------------------
// TF32 tensor-core GEMM: C = tanh(A @ W + bias).
// CTA tile 128x128, K-step 16, 256 threads = 8 warps (2 x 4), warp tile 64x32.
// Double-buffered smem; A fragments via ldmatrix.x4 (stride 20 == 4 mod 32:
// conflict-free), B fragments via scalar LDS (stride 136).
// ---------------------------------------------------------------------------
#define AS_STRIDE 20
#define BS_STRIDE 136

template<int MODE>
__global__ void __launch_bounds__(256, 2) gemm_tf32_bias_tanh(
    const float* __restrict__ A,
    const float* __restrict__ Wq, const float* __restrict__ bq,
    const float* __restrict__ Wk, const float* __restrict__ bk,
    const float* __restrict__ Wv, const float* __restrict__ bv,
    float* __restrict__ outO)
{
    __shared__ uint32_t As[2][128 * AS_STRIDE];   // [m][k], k in 0..15
    __shared__ uint32_t Bs[2][16 * BS_STRIDE];    // [k][n], n in 0..127

    const float* W;
    const float* bias;
    float* outp;
    if (MODE == 0) {
        int z = blockIdx.z;
        W    = (z == 0) ? Wq : (z == 1) ? Wk : Wv;
        bias = (z == 0) ? bq : (z == 1) ? bk : bv;
        outp = (z == 0) ? g_q : (z == 1) ? g_k : g_v;
    } else {
        W = Wq; bias = bq; outp = outO;
    }

    const int tid  = threadIdx.x;
    const int wid  = tid >> 5;
    const int lane = tid & 31;
    const int grp  = lane >> 2;       // 0..7
    const int q    = lane & 3;        // 0..3
    const int wm   = wid & 1;
    const int wn   = wid >> 1;

    const int bm = blockIdx.y * 128;
    const int bn = blockIdx.x * 128;

    const int a_row = tid >> 1;
    const int a_col = (tid & 1) * 8;
    const int b_row = tid >> 5;
    const int b_col = (tid & 31) * 4;

    const float* Aptr  = &A[(size_t)(bm + a_row) * DM + a_col];
    const float* Wptr0 = &W[(size_t)b_row * DM + bn + b_col];
    const float* Wptr1 = &W[(size_t)(b_row + 8) * DM + bn + b_col];

    // ldmatrix lane address components for the A fragment
    const int lrow = ((lane >> 3) & 1) * 8 + (lane & 7);   // row offset in frag
    const int lcol = (lane >> 4) * 4;                      // col offset in frag
    const uint32_t aLane[2] = {
        smem_u32(&As[0][0]) + (uint32_t)(((wm * 64 + lrow) * AS_STRIDE + lcol) * 4),
        smem_u32(&As[1][0]) + (uint32_t)(((wm * 64 + lrow) * AS_STRIDE + lcol) * 4)
    };

    float acc[4][4][4];
    #pragma unroll
    for (int i = 0; i < 4; i++)
        #pragma unroll
        for (int j = 0; j < 4; j++)
            #pragma unroll
            for (int r = 0; r < 4; r++) acc[i][j][r] = 0.f;

    // Prologue: load tile 0, convert, store to buffer 0
    {
        float4 ra0 = *(const float4*)&Aptr[0];
        float4 ra1 = *(const float4*)&Aptr[4];
        float4 rb0 = *(const float4*)&Wptr0[0];
        float4 rb1 = *(const float4*)&Wptr1[0];
        uint4 ua0 = make_uint4(f2tf32(ra0.x), f2tf32(ra0.y), f2tf32(ra0.z), f2tf32(ra0.w));
        uint4 ua1 = make_uint4(f2tf32(ra1.x), f2tf32(ra1.y), f2tf32(ra1.z), f2tf32(ra1.w));
        uint4 ub0 = make_uint4(f2tf32(rb0.x), f2tf32(rb0.y), f2tf32(rb0.z), f2tf32(rb0.w));
        uint4 ub1 = make_uint4(f2tf32(rb1.x), f2tf32(rb1.y), f2tf32(rb1.z), f2tf32(rb1.w));
        *(uint4*)&As[0][a_row * AS_STRIDE + a_col]     = ua0;
        *(uint4*)&As[0][a_row * AS_STRIDE + a_col + 4] = ua1;
        *(uint4*)&Bs[0][b_row * BS_STRIDE + b_col]       = ub0;
        *(uint4*)&Bs[0][(b_row + 8) * BS_STRIDE + b_col] = ub1;
    }
    __syncthreads();

    int cur = 0;
    for (int k0 = 0; k0 < DM; k0 += 16) {
        const bool has_next = (k0 + 16 < DM);
        float4 ra0, ra1, rb0, rb1;
        if (has_next) {
            int kn = k0 + 16;
            ra0 = *(const float4*)&Aptr[kn];
            ra1 = *(const float4*)&Aptr[kn + 4];
            rb0 = *(const float4*)&Wptr0[(size_t)kn * DM];
            rb1 = *(const float4*)&Wptr1[(size_t)kn * DM];
        }

        // MMAs on current buffer (overlaps the in-flight global loads)
        const uint32_t* Bc = Bs[cur];
        const uint32_t aAddr = aLane[cur];
        #pragma unroll
        for (int kk = 0; kk < 16; kk += 8) {
            uint32_t af[4][4];
            #pragma unroll
            for (int im = 0; im < 4; im++)
                ldsm_x4(af[im], aAddr + (uint32_t)((im * 16 * AS_STRIDE + kk) * 4));
            uint32_t bf[4][2];
            #pragma unroll
            for (int in_ = 0; in_ < 4; in_++) {
                int nb = wn * 32 + in_ * 8;
                bf[in_][0] = Bc[(kk + q    ) * BS_STRIDE + nb + grp];
                bf[in_][1] = Bc[(kk + q + 4) * BS_STRIDE + nb + grp];
            }
            #pragma unroll
            for (int im = 0; im < 4; im++)
                #pragma unroll
                for (int in_ = 0; in_ < 4; in_++)
                    mma_tf32(acc[im][in_], af[im], bf[in_][0], bf[in_][1]);
        }

        // Store next tile into the other buffer
        if (has_next) {
            int nxt = cur ^ 1;
            uint4 ua0 = make_uint4(f2tf32(ra0.x), f2tf32(ra0.y), f2tf32(ra0.z), f2tf32(ra0.w));
            uint4 ua1 = make_uint4(f2tf32(ra1.x), f2tf32(ra1.y), f2tf32(ra1.z), f2tf32(ra1.w));
            uint4 ub0 = make_uint4(f2tf32(rb0.x), f2tf32(rb0.y), f2tf32(rb0.z), f2tf32(rb0.w));
            uint4 ub1 = make_uint4(f2tf32(rb1.x), f2tf32(rb1.y), f2tf32(rb1.z), f2tf32(rb1.w));
            *(uint4*)&As[nxt][a_row * AS_STRIDE + a_col]     = ua0;
            *(uint4*)&As[nxt][a_row * AS_STRIDE + a_col + 4] = ua1;
            *(uint4*)&Bs[nxt][b_row * BS_STRIDE + b_col]       = ub0;
            *(uint4*)&Bs[nxt][(b_row + 8) * BS_STRIDE + b_col] = ub1;
        }
        __syncthreads();
        cur ^= 1;
    }

    #pragma unroll
    for (int im = 0; im < 4; im++) {
        #pragma unroll
        for (int in_ = 0; in_ < 4; in_++) {
            int n0 = bn + wn * 32 + in_ * 8 + 2 * q;
            float b0v = bias[n0], b1v = bias[n0 + 1];
            #pragma unroll
            for (int half = 0; half < 2; half++) {
                int m = bm + wm * 64 + im * 16 + grp + half * 8;
                float y0 = tanhf(acc[im][in_][half * 2 + 0] + b0v);
                float y1 = tanhf(acc[im][in_][half * 2 + 1] + b1v);
                if (MODE == 0) {
                    int bbi = m >> 11;
                    int s   = m & 2047;
                    int h0  = n0 >> 6;
                    int d0  = n0 & 63;
                    size_t base = (((size_t)bbi * NH + h0) * SS + s) * HD + d0;
                    outp[base]     = y0;
                    outp[base + 1] = y1;
                } else {
                    outp[(size_t)m * DM + n0]     = y0;
                    outp[(size_t)m * DM + n0 + 1] = y1;
                }
            }
        }
    }
}

// ---------------------------------------------------------------------------
// TF32 mma.sync causal flash attention. Q/K/P fragments via ldmatrix
// (strides 68 == 4 mod 32: conflict-free). V via scalar LDS (stride 72).
// ---------------------------------------------------------------------------
#define QS_STR 68
#define KS_STR 68
#define VS_STR 72
#define PS_STR 68
#define SMEM_ATTN2 ((128*QS_STR + 64*KS_STR + 64*VS_STR + 128*PS_STR) * 4)

__global__ void __launch_bounds__(256, 2) flash_attn_tf32()
{
    extern __shared__ uint32_t smu[];
    uint32_t* Qs = smu;
    uint32_t* Ks = Qs + 128 * QS_STR;
    uint32_t* Vs = Ks + 64 * KS_STR;
    uint32_t* Ps = Vs + 64 * VS_STR;

    const int tid  = threadIdx.x;
    const int wid  = tid >> 5;
    const int lane = tid & 31;
    const int grp  = lane >> 2;
    const int qq   = lane & 3;
    const int qt   = (gridDim.x - 1) - blockIdx.x;
    const int h    = blockIdx.y;
    const int b    = blockIdx.z;
    const int q0   = qt * 128;
    const int mb   = wid * 16;

    const size_t head_off = ((size_t)(b * NH + h)) * SS * HD;
    const float* Qg = g_q + head_off;
    const float* Kg = g_k + head_off;
    const float* Vg = g_v + head_off;

    // ldmatrix lane address components
    const int lrow = ((lane >> 3) & 1) * 8 + (lane & 7);   // A-frag pattern
    const int lcol = (lane >> 4) * 4;
    const int krow = ((lane >> 4) << 3) + (lane & 7);      // paired-B pattern
    const int kcol = ((lane >> 3) & 1) * 4;

    const uint32_t sbase = smem_u32(smu);
    const uint32_t qLane = sbase + (uint32_t)(((mb + lrow) * QS_STR + lcol) * 4);
    const uint32_t kLane = sbase + (uint32_t)((128 * QS_STR + krow * KS_STR + kcol) * 4);
    const uint32_t pLane = sbase + (uint32_t)((128 * QS_STR + 64 * KS_STR + 64 * VS_STR
                                               + (mb + lrow) * PS_STR + lcol) * 4);

    for (int i = tid; i < 2048; i += 256) {
        int r = i >> 4, c4 = (i & 15) * 4;
        float4 t = *(const float4*)&Qg[(size_t)(q0 + r) * HD + c4];
        uint32_t* p = &Qs[r * QS_STR + c4];
        p[0] = f2tf32(t.x); p[1] = f2tf32(t.y);
        p[2] = f2tf32(t.z); p[3] = f2tf32(t.w);
    }

    float m0 = -1e30f, m1 = -1e30f, l0 = 0.f, l1 = 0.f;
    float o[8][4];
    #pragma unroll
    for (int nf = 0; nf < 8; nf++)
        #pragma unroll
        for (int r = 0; r < 4; r++) o[nf][r] = 0.f;

    const int n_kt = 2 * qt + 2;
    const int row0 = q0 + mb + grp;
    const int row1 = row0 + 8;

    for (int kt = 0; kt < n_kt; kt++) {
        const int k0 = kt * 64;
        __syncthreads();
        for (int i = tid; i < 1024; i += 256) {
            int r = i >> 4, c4 = (i & 15) * 4;
            float4 kv = *(const float4*)&Kg[(size_t)(k0 + r) * HD + c4];
            uint32_t* pk = &Ks[r * KS_STR + c4];
            pk[0] = f2tf32(kv.x); pk[1] = f2tf32(kv.y);
            pk[2] = f2tf32(kv.z); pk[3] = f2tf32(kv.w);
            float4 vv = *(const float4*)&Vg[(size_t)(k0 + r) * HD + c4];
            uint32_t* pv = &Vs[r * VS_STR + c4];
            pv[0] = f2tf32(vv.x); pv[1] = f2tf32(vv.y);
            pv[2] = f2tf32(vv.z); pv[3] = f2tf32(vv.w);
        }
        __syncthreads();

        if (k0 > q0 + mb + 15) continue;

        float sc[8][4];
        #pragma unroll
        for (int nf = 0; nf < 8; nf++)
            #pragma unroll
            for (int r = 0; r < 4; r++) sc[nf][r] = 0.f;

        #pragma unroll
        for (int kf = 0; kf < 8; kf++) {
            uint32_t a[4];
            ldsm_x4(a, qLane + (uint32_t)(kf * 32));
            #pragma unroll
            for (int nf2 = 0; nf2 < 8; nf2 += 2) {
                uint32_t kb[4];
                ldsm_x4(kb, kLane + (uint32_t)((nf2 * 8 * KS_STR) * 4 + kf * 32));
                mma_tf32(sc[nf2],     a, kb[0], kb[1]);
                mma_tf32(sc[nf2 + 1], a, kb[2], kb[3]);
            }
        }

        const bool diag = (kt >= 2 * qt);
        float rm0 = -1e30f, rm1 = -1e30f;
        #pragma unroll
        for (int nf = 0; nf < 8; nf++) {
            int c0 = k0 + nf * 8 + 2 * qq;
            float s0v = sc[nf][0] * 0.125f;
            float s1v = sc[nf][1] * 0.125f;
            float s2v = sc[nf][2] * 0.125f;
            float s3v = sc[nf][3] * 0.125f;
            if (diag) {
                if (c0     > row0) s0v = -1e30f;
                if (c0 + 1 > row0) s1v = -1e30f;
                if (c0     > row1) s2v = -1e30f;
                if (c0 + 1 > row1) s3v = -1e30f;
            }
            sc[nf][0] = s0v; sc[nf][1] = s1v; sc[nf][2] = s2v; sc[nf][3] = s3v;
            rm0 = fmaxf(rm0, fmaxf(s0v, s1v));
            rm1 = fmaxf(rm1, fmaxf(s2v, s3v));
        }
        #pragma unroll
        for (int off = 1; off <= 2; off <<= 1) {
            rm0 = fmaxf(rm0, __shfl_xor_sync(0xffffffffu, rm0, off));
            rm1 = fmaxf(rm1, __shfl_xor_sync(0xffffffffu, rm1, off));
        }
        float mn0 = fmaxf(m0, rm0);
        float mn1 = fmaxf(m1, rm1);

        float s0 = 0.f, s1 = 0.f;
        #pragma unroll
        for (int nf = 0; nf < 8; nf++) {
            float p0 = __expf(sc[nf][0] - mn0);
            float p1 = __expf(sc[nf][1] - mn0);
            float p2 = __expf(sc[nf][2] - mn1);
            float p3 = __expf(sc[nf][3] - mn1);
            s0 += p0 + p1;
            s1 += p2 + p3;
            uint2 u01 = make_uint2(f2tf32(p0), f2tf32(p1));
            uint2 u23 = make_uint2(f2tf32(p2), f2tf32(p3));
            *(uint2*)&Ps[(mb + grp    ) * PS_STR + nf * 8 + 2 * qq] = u01;
            *(uint2*)&Ps[(mb + grp + 8) * PS_STR + nf * 8 + 2 * qq] = u23;
        }
        #pragma unroll
        for (int off = 1; off <= 2; off <<= 1) {
            s0 += __shfl_xor_sync(0xffffffffu, s0, off);
            s1 += __shfl_xor_sync(0xffffffffu, s1, off);
        }
        float a0 = __expf(m0 - mn0);
        float a1 = __expf(m1 - mn1);
        l0 = l0 * a0 + s0;
        l1 = l1 * a1 + s1;
        m0 = mn0; m1 = mn1;
        #pragma unroll
        for (int nf = 0; nf < 8; nf++) {
            o[nf][0] *= a0; o[nf][1] *= a0;
            o[nf][2] *= a1; o[nf][3] *= a1;
        }
        __syncwarp();

        #pragma unroll
        for (int kf = 0; kf < 8; kf++) {
            uint32_t a[4];
            ldsm_x4(a, pLane + (uint32_t)(kf * 32));
            #pragma unroll
            for (int nf = 0; nf < 8; nf++) {
                uint32_t b0 = Vs[(kf * 8 + qq    ) * VS_STR + nf * 8 + grp];
                uint32_t b1 = Vs[(kf * 8 + qq + 4) * VS_STR + nf * 8 + grp];
                mma_tf32(o[nf], a, b0, b1);
            }
        }
    }

    float inv0 = 1.f / l0;
    float inv1 = 1.f / l1;
    #pragma unroll
    for (int nf = 0; nf < 8; nf++) {
        int c = h * HD + nf * 8 + 2 * qq;
        *(float2*)&g_ctx[((size_t)b * SS + row0) * DM + c] =
            make_float2(o[nf][0] * inv0, o[nf][1] * inv0);
        *(float2*)&g_ctx[((size_t)b * SS + row1) * DM + c] =
            make_float2(o[nf][2] * inv1, o[nf][3] * inv1);
    }
}

// ---------------------------------------------------------------------------
extern "C" void kernel_launch(void* const* d_in, const int* in_sizes, int n_in,
                              void* d_out, int out_size)
{
    const float* states = (const float*)d_in[0];
    const float* Wq = (const float*)d_in[1];
    const float* bq = (const float*)d_in[2];
    const float* Wk = (const float*)d_in[3];
    const float* bk = (const float*)d_in[4];
    const float* Wv = (const float*)d_in[5];
    const float* bv = (const float*)d_in[6];
    const float* Wo = (const float*)d_in[7];
    const float* bo = (const float*)d_in[8];
    float* out = (float*)d_out;

    float* ctx_ptr = nullptr;
    cudaGetSymbolAddress((void**)&ctx_ptr, g_ctx);
    cudaFuncSetAttribute(flash_attn_tf32,
                         cudaFuncAttributeMaxDynamicSharedMemorySize, SMEM_ATTN2);

    // 1) QKV projections (fused over z), tensor-core TF32
    dim3 gq(DM / 128, MT / 128, 3);
    gemm_tf32_bias_tanh<0><<<gq, 256>>>(states, Wq, bq, Wk, bk, Wv, bv, nullptr);

    // 2) causal flash attention, tensor-core TF32
    dim3 ga(SS / 128, NH, BB);
    flash_attn_tf32<<<ga, 256, SMEM_ATTN2>>>();

    // 3) output projection
    dim3 go(DM / 128, MT / 128, 1);
    gemm_tf32_bias_tanh<1><<<go, 256>>>(ctx_ptr, Wo, bo, Wo, bo, Wo, bo, out);
}

// round 8
// speedup vs baseline: 3.0227x; 1.0930x over previous
#include <cuda_runtime.h>
#include <math.h>
#include <stdint.h>

#define BB 2
#define SS 2048
#define DM 1024
#define NH 16
#define HD 64
#define MT (BB*SS)   // 4096 rows total

// Scratch (allocation-free). Values stored as tf32 bit patterns (uint32).
__device__ uint32_t g_a32[MT*DM];        // states, tf32 bits
__device__ uint32_t g_w32[4*DM*DM];      // Wq|Wk|Wv|Wo, tf32 bits
__device__ uint32_t g_q[BB*NH*SS*HD];    // tanh(qkv) as tf32 bits
__device__ uint32_t g_k[BB*NH*SS*HD];
__device__ uint32_t g_v[BB*NH*SS*HD];
__device__ uint32_t g_ctx[MT*DM];        // attention out as tf32 bits

__device__ __forceinline__ uint32_t f2tf32(float f) {
    uint32_t r;
    asm("cvt.rna.tf32.f32 %0, %1;" : "=r"(r) : "f"(f));
    return r;
}

__device__ __forceinline__ uint32_t smem_u32(const void* p) {
    uint32_t a;
    asm("{ .reg .u64 t; cvta.to.shared.u64 t, %1; cvt.u32.u64 %0, t; }"
        : "=r"(a) : "l"(p));
    return a;
}

__device__ __forceinline__ void mma_tf32(float* c, const uint32_t* a,
                                         uint32_t b0, uint32_t b1) {
    asm volatile(
        "mma.sync.aligned.m16n8k8.row.col.f32.tf32.tf32.f32 "
        "{%0,%1,%2,%3},{%4,%5,%6,%7},{%8,%9},{%0,%1,%2,%3};\n"
        : "+f"(c[0]), "+f"(c[1]), "+f"(c[2]), "+f"(c[3])
        : "r"(a[0]), "r"(a[1]), "r"(a[2]), "r"(a[3]), "r"(b0), "r"(b1));
}

__device__ __forceinline__ void ldsm_x4(uint32_t* r, uint32_t saddr) {
    asm volatile(
        "ldmatrix.sync.aligned.m8n8.x4.shared.b16 {%0,%1,%2,%3}, [%4];"
        : "=r"(r[0]), "=r"(r[1]), "=r"(r[2]), "=r"(r[3])
        : "r"(saddr));
}

#define CP16(dst, src) \
    asm volatile("cp.async.cg.shared.global [%0], [%1], 16;" \
                 :: "r"(dst), "l"(src))
#define CP_COMMIT() asm volatile("cp.async.commit_group;" ::: "memory")
#define CP_WAIT(n)  asm volatile("cp.async.wait_group %0;" :: "n"(n) : "memory")

// ---------------------------------------------------------------------------
// Pre-convert: states + 4 weight matrices -> tf32 bits.
// ---------------------------------------------------------------------------
__global__ void __launch_bounds__(256) convert_inputs(
    const float* __restrict__ states,
    const float* __restrict__ Wq, const float* __restrict__ Wk,
    const float* __restrict__ Wv, const float* __restrict__ Wo)
{
    size_t idx = (size_t)blockIdx.x * blockDim.x + threadIdx.x;  // float4 index
    const float* src;
    uint32_t* dst;
    size_t off;
    if (idx < 1048576) {                 // states: 4096x1024 = 1M float4
        src = states; dst = g_a32; off = idx;
    } else {
        size_t j = idx - 1048576;
        int w = (int)(j >> 18);          // 262144 float4 per 1024x1024 W
        off = j & 262143;
        src = (w == 0) ? Wq : (w == 1) ? Wk : (w == 2) ? Wv : Wo;
        dst = g_w32 + (size_t)w * 1048576;
    }
    float4 v = *(const float4*)(src + off * 4);
    uint4 u = make_uint4(f2tf32(v.x), f2tf32(v.y), f2tf32(v.z), f2tf32(v.w));
    *(uint4*)(dst + off * 4) = u;
}

// ---------------------------------------------------------------------------
// TF32 tensor-core GEMM on pre-converted operands: C = tanh(A @ W + bias).
// CTA tile 128x128, K-step 16, 4-stage cp.async pipeline, 8 warps 64x32.
// MODE 0: W = g_w32+z*1M, out -> g_q/g_k/g_v (tf32 bits, [B,H,S,D] layout).
// MODE 1: A = g_ctx, W = Wo slot, out -> float d_out.
// ---------------------------------------------------------------------------
#define AS_STRIDE 20
#define BS_STRIDE 136
#define STAGES 4
#define A_STG (128 * AS_STRIDE)          // u32 per A stage (10240 B)
#define B_STG (16 * BS_STRIDE)           // u32 per B stage (8704 B)
#define GEMM_SMEM (STAGES * (A_STG + B_STG) * 4)   // 75776 B

template<int MODE>
__global__ void __launch_bounds__(256, 2) gemm_tf32_bias_tanh(
    const uint32_t* __restrict__ Abase,
    const float* __restrict__ bq, const float* __restrict__ bk,
    const float* __restrict__ bv,
    float* __restrict__ outO)
{
    extern __shared__ uint32_t dsm[];
    uint32_t* smA = dsm;                         // [STAGES][A_STG]
    uint32_t* smB = dsm + STAGES * A_STG;        // [STAGES][B_STG]
    const uint32_t smA_u = smem_u32(smA);
    const uint32_t smB_u = smem_u32(smB);

    const uint32_t* W;
    const float* bias;
    uint32_t* outq;
    if (MODE == 0) {
        int z = blockIdx.z;
        W    = g_w32 + (size_t)z * (DM * DM);
        bias = (z == 0) ? bq : (z == 1) ? bk : bv;
        outq = (z == 0) ? g_q : (z == 1) ? g_k : g_v;
    } else {
        W = g_w32 + (size_t)3 * (DM * DM);
        bias = bq;           // bo passed in bq slot
        outq = nullptr;
    }

    const int tid  = threadIdx.x;
    const int wid  = tid >> 5;
    const int lane = tid & 31;
    const int grp  = lane >> 2;
    const int q    = lane & 3;
    const int wm   = wid & 1;
    const int wn   = wid >> 1;

    const int bm = blockIdx.y * 128;
    const int bn = blockIdx.x * 128;

    const int a_row = tid >> 1;
    const int a_col = (tid & 1) * 8;
    const int b_row = tid >> 5;
    const int b_col = (tid & 31) * 4;

    const uint32_t* Aptr = Abase + (size_t)(bm + a_row) * DM + a_col;
    const uint32_t* Wp0  = W + (size_t)b_row * DM + bn + b_col;
    const uint32_t* Wp1  = W + (size_t)(b_row + 8) * DM + bn + b_col;

    const uint32_t aoff = (uint32_t)((a_row * AS_STRIDE + a_col) * 4);
    const uint32_t boff = (uint32_t)((b_row * BS_STRIDE + b_col) * 4);

    // ldmatrix lane address base for A fragments
    const int lrow = ((lane >> 3) & 1) * 8 + (lane & 7);
    const int lcol = (lane >> 4) * 4;
    const uint32_t aFragOff = (uint32_t)(((wm * 64 + lrow) * AS_STRIDE + lcol) * 4);

    float acc[4][4][4];
    #pragma unroll
    for (int i = 0; i < 4; i++)
        #pragma unroll
        for (int j = 0; j < 4; j++)
            #pragma unroll
            for (int r = 0; r < 4; r++) acc[i][j][r] = 0.f;

    // Prologue: issue stages 0..2
    #pragma unroll
    for (int s = 0; s < STAGES - 1; s++) {
        uint32_t aB = smA_u + (uint32_t)(s * A_STG * 4) + aoff;
        uint32_t bB = smB_u + (uint32_t)(s * B_STG * 4) + boff;
        const uint32_t* sa = Aptr + s * 16;
        CP16(aB, sa);
        CP16(aB + 16, sa + 4);
        CP16(bB, Wp0 + (size_t)s * 16 * DM);
        CP16(bB + 8 * BS_STRIDE * 4, Wp1 + (size_t)s * 16 * DM);
        CP_COMMIT();
    }

    for (int i = 0; i < DM / 16; i++) {
        CP_WAIT(2);            // stage i data complete (this thread)
        __syncthreads();       // all threads' stage-i data visible; prev reads done

        // Issue load for stage i+3 (overwrites stage (i-1)&3 — safe after sync)
        int pre = i + STAGES - 1;
        if (pre < DM / 16) {
            int s = pre & (STAGES - 1);
            uint32_t aB = smA_u + (uint32_t)(s * A_STG * 4) + aoff;
            uint32_t bB = smB_u + (uint32_t)(s * B_STG * 4) + boff;
            const uint32_t* sa = Aptr + pre * 16;
            CP16(aB, sa);
            CP16(aB + 16, sa + 4);
            CP16(bB, Wp0 + (size_t)pre * 16 * DM);
            CP16(bB + 8 * BS_STRIDE * 4, Wp1 + (size_t)pre * 16 * DM);
        }
        CP_COMMIT();

        // MMAs on stage i
        const int st = i & (STAGES - 1);
        const uint32_t aAddr = smA_u + (uint32_t)(st * A_STG * 4) + aFragOff;
        const uint32_t* Bc = smB + st * B_STG;
        #pragma unroll
        for (int kk = 0; kk < 16; kk += 8) {
            uint32_t af[4][4];
            #pragma unroll
            for (int im = 0; im < 4; im++)
                ldsm_x4(af[im], aAddr + (uint32_t)((im * 16 * AS_STRIDE + kk) * 4));
            uint32_t bf[4][2];
            #pragma unroll
            for (int in_ = 0; in_ < 4; in_++) {
                int nb = wn * 32 + in_ * 8;
                bf[in_][0] = Bc[(kk + q    ) * BS_STRIDE + nb + grp];
                bf[in_][1] = Bc[(kk + q + 4) * BS_STRIDE + nb + grp];
            }
            #pragma unroll
            for (int im = 0; im < 4; im++)
                #pragma unroll
                for (int in_ = 0; in_ < 4; in_++)
                    mma_tf32(acc[im][in_], af[im], bf[in_][0], bf[in_][1]);
        }
    }

    // Epilogue: bias + tanh
    #pragma unroll
    for (int im = 0; im < 4; im++) {
        #pragma unroll
        for (int in_ = 0; in_ < 4; in_++) {
            int n0 = bn + wn * 32 + in_ * 8 + 2 * q;
            float b0v = bias[n0], b1v = bias[n0 + 1];
            #pragma unroll
            for (int half = 0; half < 2; half++) {
                int m = bm + wm * 64 + im * 16 + grp + half * 8;
                float y0 = tanhf(acc[im][in_][half * 2 + 0] + b0v);
                float y1 = tanhf(acc[im][in_][half * 2 + 1] + b1v);
                if (MODE == 0) {
                    int bbi = m >> 11;
                    int s   = m & 2047;
                    int h0  = n0 >> 6;
                    int d0  = n0 & 63;
                    size_t base = (((size_t)bbi * NH + h0) * SS + s) * HD + d0;
                    outq[base]     = f2tf32(y0);
                    outq[base + 1] = f2tf32(y1);
                } else {
                    outO[(size_t)m * DM + n0]     = y0;
                    outO[(size_t)m * DM + n0 + 1] = y1;
                }
            }
        }
    }
}

// ---------------------------------------------------------------------------
// TF32 mma.sync causal flash attention. Q/K/V arrive pre-converted (tf32
// bits) -> cp.async straight to smem, zero conversions in the loop.
// ---------------------------------------------------------------------------
#define QS_STR 68
#define KS_STR 68
#define VS_STR 72
#define PS_STR 68
#define SMEM_ATTN2 ((128*QS_STR + 64*KS_STR + 64*VS_STR + 128*PS_STR) * 4)

__global__ void __launch_bounds__(256, 2) flash_attn_tf32()
{
    extern __shared__ uint32_t smu[];
    uint32_t* Ps = smu + 128 * QS_STR + 64 * KS_STR + 64 * VS_STR;

    const int tid  = threadIdx.x;
    const int wid  = tid >> 5;
    const int lane = tid & 31;
    const int grp  = lane >> 2;
    const int qq   = lane & 3;
    const int qt   = (gridDim.x - 1) - blockIdx.x;
    const int h    = blockIdx.y;
    const int b    = blockIdx.z;
    const int q0   = qt * 128;
    const int mb   = wid * 16;

    const size_t head_off = ((size_t)(b * NH + h)) * SS * HD;
    const uint32_t* Qg = g_q + head_off;
    const uint32_t* Kg = g_k + head_off;
    const uint32_t* Vg = g_v + head_off;

    const uint32_t sbase = smem_u32(smu);
    const uint32_t ksm = sbase + 128 * QS_STR * 4;
    const uint32_t vsm = ksm + 64 * KS_STR * 4;

    const int lrow = ((lane >> 3) & 1) * 8 + (lane & 7);
    const int lcol = (lane >> 4) * 4;
    const int krow = ((lane >> 4) << 3) + (lane & 7);
    const int kcol = ((lane >> 3) & 1) * 4;

    const uint32_t qLane = sbase + (uint32_t)(((mb + lrow) * QS_STR + lcol) * 4);
    const uint32_t kLane = ksm + (uint32_t)((krow * KS_STR + kcol) * 4);
    const uint32_t pLane = sbase + (uint32_t)((128 * QS_STR + 64 * KS_STR + 64 * VS_STR
                                               + (mb + lrow) * PS_STR + lcol) * 4);

    // Q tile via cp.async (2048 16B chunks over 256 threads)
    for (int i = tid; i < 2048; i += 256) {
        int r = i >> 4, c4 = (i & 15) * 4;
        CP16(sbase + (uint32_t)((r * QS_STR + c4) * 4),
             Qg + (size_t)(q0 + r) * HD + c4);
    }
    CP_COMMIT();

    float m0 = -1e30f, m1 = -1e30f, l0 = 0.f, l1 = 0.f;
    float o[8][4];
    #pragma unroll
    for (int nf = 0; nf < 8; nf++)
        #pragma unroll
        for (int r = 0; r < 4; r++) o[nf][r] = 0.f;

    const int n_kt = 2 * qt + 2;
    const int row0 = q0 + mb + grp;
    const int row1 = row0 + 8;

    for (int kt = 0; kt < n_kt; kt++) {
        const int k0 = kt * 64;
        __syncthreads();       // previous tile's reads done before overwrite
        for (int i = tid; i < 1024; i += 256) {
            int r = i >> 4, c4 = (i & 15) * 4;
            const size_t src = (size_t)(k0 + r) * HD + c4;
            CP16(ksm + (uint32_t)((r * KS_STR + c4) * 4), Kg + src);
            CP16(vsm + (uint32_t)((r * VS_STR + c4) * 4), Vg + src);
        }
        CP_COMMIT();
        CP_WAIT(0);
        __syncthreads();

        if (k0 > q0 + mb + 15) continue;

        float sc[8][4];
        #pragma unroll
        for (int nf = 0; nf < 8; nf++)
            #pragma unroll
            for (int r = 0; r < 4; r++) sc[nf][r] = 0.f;

        #pragma unroll
        for (int kf = 0; kf < 8; kf++) {
            uint32_t a[4];
            ldsm_x4(a, qLane + (uint32_t)(kf * 32));
            #pragma unroll
            for (int nf2 = 0; nf2 < 8; nf2 += 2) {
                uint32_t kb[4];
                ldsm_x4(kb, kLane + (uint32_t)((nf2 * 8 * KS_STR) * 4 + kf * 32));
                mma_tf32(sc[nf2],     a, kb[0], kb[1]);
                mma_tf32(sc[nf2 + 1], a, kb[2], kb[3]);
            }
        }

        const bool diag = (kt >= 2 * qt);
        float rm0 = -1e30f, rm1 = -1e30f;
        #pragma unroll
        for (int nf = 0; nf < 8; nf++) {
            int c0 = k0 + nf * 8 + 2 * qq;
            float s0v = sc[nf][0] * 0.125f;
            float s1v = sc[nf][1] * 0.125f;
            float s2v = sc[nf][2] * 0.125f;
            float s3v = sc[nf][3] * 0.125f;
            if (diag) {
                if (c0     > row0) s0v = -1e30f;
                if (c0 + 1 > row0) s1v = -1e30f;
                if (c0     > row1) s2v = -1e30f;
                if (c0 + 1 > row1) s3v = -1e30f;
            }
            sc[nf][0] = s0v; sc[nf][1] = s1v; sc[nf][2] = s2v; sc[nf][3] = s3v;
            rm0 = fmaxf(rm0, fmaxf(s0v, s1v));
            rm1 = fmaxf(rm1, fmaxf(s2v, s3v));
        }
        #pragma unroll
        for (int off = 1; off <= 2; off <<= 1) {
            rm0 = fmaxf(rm0, __shfl_xor_sync(0xffffffffu, rm0, off));
            rm1 = fmaxf(rm1, __shfl_xor_sync(0xffffffffu, rm1, off));
        }
        float mn0 = fmaxf(m0, rm0);
        float mn1 = fmaxf(m1, rm1);

        float s0 = 0.f, s1 = 0.f;
        #pragma unroll
        for (int nf = 0; nf < 8; nf++) {
            float p0 = __expf(sc[nf][0] - mn0);
            float p1 = __expf(sc[nf][1] - mn0);
            float p2 = __expf(sc[nf][2] - mn1);
            float p3 = __expf(sc[nf][3] - mn1);
            s0 += p0 + p1;
            s1 += p2 + p3;
            uint2 u01 = make_uint2(f2tf32(p0), f2tf32(p1));
            uint2 u23 = make_uint2(f2tf32(p2), f2tf32(p3));
            *(uint2*)&Ps[(mb + grp    ) * PS_STR + nf * 8 + 2 * qq] = u01;
            *(uint2*)&Ps[(mb + grp + 8) * PS_STR + nf * 8 + 2 * qq] = u23;
        }
        #pragma unroll
        for (int off = 1; off <= 2; off <<= 1) {
            s0 += __shfl_xor_sync(0xffffffffu, s0, off);
            s1 += __shfl_xor_sync(0xffffffffu, s1, off);
        }
        float a0 = __expf(m0 - mn0);
        float a1 = __expf(m1 - mn1);
        l0 = l0 * a0 + s0;
        l1 = l1 * a1 + s1;
        m0 = mn0; m1 = mn1;
        #pragma unroll
        for (int nf = 0; nf < 8; nf++) {
            o[nf][0] *= a0; o[nf][1] *= a0;
            o[nf][2] *= a1; o[nf][3] *= a1;
        }
        __syncwarp();

        const uint32_t* Vs = smu + 128 * QS_STR + 64 * KS_STR;
        #pragma unroll
        for (int kf = 0; kf < 8; kf++) {
            uint32_t a[4];
            ldsm_x4(a, pLane + (uint32_t)(kf * 32));
            #pragma unroll
            for (int nf = 0; nf < 8; nf++) {
                uint32_t b0 = Vs[(kf * 8 + qq    ) * VS_STR + nf * 8 + grp];
                uint32_t b1 = Vs[(kf * 8 + qq + 4) * VS_STR + nf * 8 + grp];
                mma_tf32(o[nf], a, b0, b1);
            }
        }
    }

    // finalize; ctx written as tf32 bits for the O-proj GEMM
    float inv0 = 1.f / l0;
    float inv1 = 1.f / l1;
    #pragma unroll
    for (int nf = 0; nf < 8; nf++) {
        int c = h * HD + nf * 8 + 2 * qq;
        *(uint2*)&g_ctx[((size_t)b * SS + row0) * DM + c] =
            make_uint2(f2tf32(o[nf][0] * inv0), f2tf32(o[nf][1] * inv0));
        *(uint2*)&g_ctx[((size_t)b * SS + row1) * DM + c] =
            make_uint2(f2tf32(o[nf][2] * inv1), f2tf32(o[nf][3] * inv1));
    }
}

// ---------------------------------------------------------------------------
extern "C" void kernel_launch(void* const* d_in, const int* in_sizes, int n_in,
                              void* d_out, int out_size)
{
    const float* states = (const float*)d_in[0];
    const float* Wq = (const float*)d_in[1];
    const float* bq = (const float*)d_in[2];
    const float* Wk = (const float*)d_in[3];
    const float* bk = (const float*)d_in[4];
    const float* Wv = (const float*)d_in[5];
    const float* bv = (const float*)d_in[6];
    const float* bo = (const float*)d_in[8];
    float* out = (float*)d_out;

    uint32_t* a32_ptr = nullptr;
    uint32_t* ctx_ptr = nullptr;
    cudaGetSymbolAddress((void**)&a32_ptr, g_a32);
    cudaGetSymbolAddress((void**)&ctx_ptr, g_ctx);

    cudaFuncSetAttribute(gemm_tf32_bias_tanh<0>,
                         cudaFuncAttributeMaxDynamicSharedMemorySize, GEMM_SMEM);
    cudaFuncSetAttribute(gemm_tf32_bias_tanh<1>,
                         cudaFuncAttributeMaxDynamicSharedMemorySize, GEMM_SMEM);
    cudaFuncSetAttribute(flash_attn_tf32,
                         cudaFuncAttributeMaxDynamicSharedMemorySize, SMEM_ATTN2);

    // 0) convert states + weights to tf32 bits
    convert_inputs<<<8192, 256>>>(states, Wq, Wk, Wv, (const float*)d_in[7]);

    // 1) QKV projections (fused over z)
    dim3 gq(DM / 128, MT / 128, 3);
    gemm_tf32_bias_tanh<0><<<gq, 256, GEMM_SMEM>>>(a32_ptr, bq, bk, bv, nullptr);

    // 2) causal flash attention
    dim3 ga(SS / 128, NH, BB);
    flash_attn_tf32<<<ga, 256, SMEM_ATTN2>>>();

    // 3) output projection
    dim3 go(DM / 128, MT / 128, 1);
    gemm_tf32_bias_tanh<1><<<go, 256, GEMM_SMEM>>>(ctx_ptr, bo, nullptr, nullptr, out);
}

// round 9
// speedup vs baseline: 3.1671x; 1.0478x over previous
#include <cuda_runtime.h>
#include <math.h>
#include <stdint.h>

#define BB 2
#define SS 2048
#define DM 1024
#define NH 16
#define HD 64
#define MT (BB*SS)   // 4096 rows total

// Scratch (allocation-free). Values stored as tf32 bit patterns (uint32).
__device__ uint32_t g_a32[MT*DM];        // states, tf32 bits
__device__ uint32_t g_w32[4*DM*DM];      // Wq|Wk|Wv|Wo, tf32 bits
__device__ uint32_t g_q[BB*NH*SS*HD];    // tanh(qkv) as tf32 bits
__device__ uint32_t g_k[BB*NH*SS*HD];
__device__ uint32_t g_v[BB*NH*SS*HD];
__device__ uint32_t g_ctx[MT*DM];        // attention out as tf32 bits

__device__ __forceinline__ uint32_t f2tf32(float f) {
    uint32_t r;
    asm("cvt.rna.tf32.f32 %0, %1;" : "=r"(r) : "f"(f));
    return r;
}

__device__ __forceinline__ uint32_t smem_u32(const void* p) {
    uint32_t a;
    asm("{ .reg .u64 t; cvta.to.shared.u64 t, %1; cvt.u32.u64 %0, t; }"
        : "=r"(a) : "l"(p));
    return a;
}

__device__ __forceinline__ void mma_tf32(float* c, const uint32_t* a,
                                         uint32_t b0, uint32_t b1) {
    asm volatile(
        "mma.sync.aligned.m16n8k8.row.col.f32.tf32.tf32.f32 "
        "{%0,%1,%2,%3},{%4,%5,%6,%7},{%8,%9},{%0,%1,%2,%3};\n"
        : "+f"(c[0]), "+f"(c[1]), "+f"(c[2]), "+f"(c[3])
        : "r"(a[0]), "r"(a[1]), "r"(a[2]), "r"(a[3]), "r"(b0), "r"(b1));
}

__device__ __forceinline__ void ldsm_x4(uint32_t* r, uint32_t saddr) {
    asm volatile(
        "ldmatrix.sync.aligned.m8n8.x4.shared.b16 {%0,%1,%2,%3}, [%4];"
        : "=r"(r[0]), "=r"(r[1]), "=r"(r[2]), "=r"(r[3])
        : "r"(saddr));
}

#define CP16(dst, src) \
    asm volatile("cp.async.cg.shared.global [%0], [%1], 16;" \
                 :: "r"(dst), "l"(src))
#define CP_COMMIT() asm volatile("cp.async.commit_group;" ::: "memory")
#define CP_WAIT(n)  asm volatile("cp.async.wait_group %0;" :: "n"(n) : "memory")

// ---------------------------------------------------------------------------
// Pre-convert: states + 4 weight matrices -> tf32 bits.
// ---------------------------------------------------------------------------
__global__ void __launch_bounds__(256) convert_inputs(
    const float* __restrict__ states,
    const float* __restrict__ Wq, const float* __restrict__ Wk,
    const float* __restrict__ Wv, const float* __restrict__ Wo)
{
    size_t idx = (size_t)blockIdx.x * blockDim.x + threadIdx.x;  // float4 index
    const float* src;
    uint32_t* dst;
    size_t off;
    if (idx < 1048576) {                 // states: 4096x1024 = 1M float4
        src = states; dst = g_a32; off = idx;
    } else {
        size_t j = idx - 1048576;
        int w = (int)(j >> 18);          // 262144 float4 per 1024x1024 W
        off = j & 262143;
        src = (w == 0) ? Wq : (w == 1) ? Wk : (w == 2) ? Wv : Wo;
        dst = g_w32 + (size_t)w * 1048576;
    }
    float4 v = *(const float4*)(src + off * 4);
    uint4 u = make_uint4(f2tf32(v.x), f2tf32(v.y), f2tf32(v.z), f2tf32(v.w));
    *(uint4*)(dst + off * 4) = u;
}

// ---------------------------------------------------------------------------
// TF32 tensor-core GEMM on pre-converted operands: C = tanh(A @ W + bias).
// CTA tile 128x128, K-step 16, 4-stage cp.async pipeline, 8 warps 64x32.
// ---------------------------------------------------------------------------
#define AS_STRIDE 20
#define BS_STRIDE 136
#define STAGES 4
#define A_STG (128 * AS_STRIDE)
#define B_STG (16 * BS_STRIDE)
#define GEMM_SMEM (STAGES * (A_STG + B_STG) * 4)

template<int MODE>
__global__ void __launch_bounds__(256, 2) gemm_tf32_bias_tanh(
    const uint32_t* __restrict__ Abase,
    const float* __restrict__ bq, const float* __restrict__ bk,
    const float* __restrict__ bv,
    float* __restrict__ outO)
{
    extern __shared__ uint32_t dsm[];
    uint32_t* smA = dsm;
    uint32_t* smB = dsm + STAGES * A_STG;
    const uint32_t smA_u = smem_u32(smA);
    const uint32_t smB_u = smem_u32(smB);

    const uint32_t* W;
    const float* bias;
    uint32_t* outq;
    if (MODE == 0) {
        int z = blockIdx.z;
        W    = g_w32 + (size_t)z * (DM * DM);
        bias = (z == 0) ? bq : (z == 1) ? bk : bv;
        outq = (z == 0) ? g_q : (z == 1) ? g_k : g_v;
    } else {
        W = g_w32 + (size_t)3 * (DM * DM);
        bias = bq;
        outq = nullptr;
    }

    const int tid  = threadIdx.x;
    const int wid  = tid >> 5;
    const int lane = tid & 31;
    const int grp  = lane >> 2;
    const int q    = lane & 3;
    const int wm   = wid & 1;
    const int wn   = wid >> 1;

    const int bm = blockIdx.y * 128;
    const int bn = blockIdx.x * 128;

    const int a_row = tid >> 1;
    const int a_col = (tid & 1) * 8;
    const int b_row = tid >> 5;
    const int b_col = (tid & 31) * 4;

    const uint32_t* Aptr = Abase + (size_t)(bm + a_row) * DM + a_col;
    const uint32_t* Wp0  = W + (size_t)b_row * DM + bn + b_col;
    const uint32_t* Wp1  = W + (size_t)(b_row + 8) * DM + bn + b_col;

    const uint32_t aoff = (uint32_t)((a_row * AS_STRIDE + a_col) * 4);
    const uint32_t boff = (uint32_t)((b_row * BS_STRIDE + b_col) * 4);

    const int lrow = ((lane >> 3) & 1) * 8 + (lane & 7);
    const int lcol = (lane >> 4) * 4;
    const uint32_t aFragOff = (uint32_t)(((wm * 64 + lrow) * AS_STRIDE + lcol) * 4);

    float acc[4][4][4];
    #pragma unroll
    for (int i = 0; i < 4; i++)
        #pragma unroll
        for (int j = 0; j < 4; j++)
            #pragma unroll
            for (int r = 0; r < 4; r++) acc[i][j][r] = 0.f;

    #pragma unroll
    for (int s = 0; s < STAGES - 1; s++) {
        uint32_t aB = smA_u + (uint32_t)(s * A_STG * 4) + aoff;
        uint32_t bB = smB_u + (uint32_t)(s * B_STG * 4) + boff;
        const uint32_t* sa = Aptr + s * 16;
        CP16(aB, sa);
        CP16(aB + 16, sa + 4);
        CP16(bB, Wp0 + (size_t)s * 16 * DM);
        CP16(bB + 8 * BS_STRIDE * 4, Wp1 + (size_t)s * 16 * DM);
        CP_COMMIT();
    }

    for (int i = 0; i < DM / 16; i++) {
        CP_WAIT(2);
        __syncthreads();

        int pre = i + STAGES - 1;
        if (pre < DM / 16) {
            int s = pre & (STAGES - 1);
            uint32_t aB = smA_u + (uint32_t)(s * A_STG * 4) + aoff;
            uint32_t bB = smB_u + (uint32_t)(s * B_STG * 4) + boff;
            const uint32_t* sa = Aptr + pre * 16;
            CP16(aB, sa);
            CP16(aB + 16, sa + 4);
            CP16(bB, Wp0 + (size_t)pre * 16 * DM);
            CP16(bB + 8 * BS_STRIDE * 4, Wp1 + (size_t)pre * 16 * DM);
        }
        CP_COMMIT();

        const int st = i & (STAGES - 1);
        const uint32_t aAddr = smA_u + (uint32_t)(st * A_STG * 4) + aFragOff;
        const uint32_t* Bc = smB + st * B_STG;
        #pragma unroll
        for (int kk = 0; kk < 16; kk += 8) {
            uint32_t af[4][4];
            #pragma unroll
            for (int im = 0; im < 4; im++)
                ldsm_x4(af[im], aAddr + (uint32_t)((im * 16 * AS_STRIDE + kk) * 4));
            uint32_t bf[4][2];
            #pragma unroll
            for (int in_ = 0; in_ < 4; in_++) {
                int nb = wn * 32 + in_ * 8;
                bf[in_][0] = Bc[(kk + q    ) * BS_STRIDE + nb + grp];
                bf[in_][1] = Bc[(kk + q + 4) * BS_STRIDE + nb + grp];
            }
            #pragma unroll
            for (int im = 0; im < 4; im++)
                #pragma unroll
                for (int in_ = 0; in_ < 4; in_++)
                    mma_tf32(acc[im][in_], af[im], bf[in_][0], bf[in_][1]);
        }
    }

    #pragma unroll
    for (int im = 0; im < 4; im++) {
        #pragma unroll
        for (int in_ = 0; in_ < 4; in_++) {
            int n0 = bn + wn * 32 + in_ * 8 + 2 * q;
            float b0v = bias[n0], b1v = bias[n0 + 1];
            #pragma unroll
            for (int half = 0; half < 2; half++) {
                int m = bm + wm * 64 + im * 16 + grp + half * 8;
                float y0 = tanhf(acc[im][in_][half * 2 + 0] + b0v);
                float y1 = tanhf(acc[im][in_][half * 2 + 1] + b1v);
                if (MODE == 0) {
                    int bbi = m >> 11;
                    int s   = m & 2047;
                    int h0  = n0 >> 6;
                    int d0  = n0 & 63;
                    size_t base = (((size_t)bbi * NH + h0) * SS + s) * HD + d0;
                    outq[base]     = f2tf32(y0);
                    outq[base + 1] = f2tf32(y1);
                } else {
                    outO[(size_t)m * DM + n0]     = y0;
                    outO[(size_t)m * DM + n0 + 1] = y1;
                }
            }
        }
    }
}

// ---------------------------------------------------------------------------
// TF32 mma.sync causal flash attention.
// Double-buffered K/V (2-stage cp.async). P never touches smem: the S-tile
// C-fragment becomes the P A-fragment via column permutation pi(q)=2q,
// pi(q+4)=2q+1, with V's B-fragment rows permuted identically (rows 2q,2q+1).
// Smem: Q[128x68] + 2x K[64x68] + 2x V[64x68] = 102KB -> 2 CTAs/SM.
// ---------------------------------------------------------------------------
#define QS_STR 68
#define KS_STR 68
#define VS_STR 68
#define Q_U32   (128 * QS_STR)
#define K_U32   (64 * KS_STR)
#define V_U32   (64 * VS_STR)
#define SMEM_ATTN2 ((Q_U32 + 2*K_U32 + 2*V_U32) * 4)

__global__ void __launch_bounds__(256, 2) flash_attn_tf32()
{
    extern __shared__ uint32_t smu[];

    const int tid  = threadIdx.x;
    const int wid  = tid >> 5;
    const int lane = tid & 31;
    const int grp  = lane >> 2;
    const int qq   = lane & 3;
    const int qt   = (gridDim.x - 1) - blockIdx.x;
    const int h    = blockIdx.y;
    const int b    = blockIdx.z;
    const int q0   = qt * 128;
    const int mb   = wid * 16;

    const size_t head_off = ((size_t)(b * NH + h)) * SS * HD;
    const uint32_t* Qg = g_q + head_off;
    const uint32_t* Kg = g_k + head_off;
    const uint32_t* Vg = g_v + head_off;

    const uint32_t sbase = smem_u32(smu);
    const uint32_t kBuf[2] = { sbase + Q_U32 * 4, sbase + (Q_U32 + K_U32) * 4 };
    const uint32_t vBuf[2] = { sbase + (Q_U32 + 2 * K_U32) * 4,
                               sbase + (Q_U32 + 2 * K_U32 + V_U32) * 4 };

    const int lrow = ((lane >> 3) & 1) * 8 + (lane & 7);
    const int lcol = (lane >> 4) * 4;
    const int krow = ((lane >> 4) << 3) + (lane & 7);
    const int kcol = ((lane >> 3) & 1) * 4;

    const uint32_t qLane = sbase + (uint32_t)(((mb + lrow) * QS_STR + lcol) * 4);

    // Q tile via cp.async (group 1)
    for (int i = tid; i < 2048; i += 256) {
        int r = i >> 4, c4 = (i & 15) * 4;
        CP16(sbase + (uint32_t)((r * QS_STR + c4) * 4),
             Qg + (size_t)(q0 + r) * HD + c4);
    }
    CP_COMMIT();

    // K/V tile 0 into buffer 0 (group 2)
    for (int i = tid; i < 1024; i += 256) {
        int r = i >> 4, c4 = (i & 15) * 4;
        const size_t src = (size_t)r * HD + c4;
        CP16(kBuf[0] + (uint32_t)((r * KS_STR + c4) * 4), Kg + src);
        CP16(vBuf[0] + (uint32_t)((r * VS_STR + c4) * 4), Vg + src);
    }
    CP_COMMIT();

    float m0 = -1e30f, m1 = -1e30f, l0 = 0.f, l1 = 0.f;
    float o[8][4];
    #pragma unroll
    for (int nf = 0; nf < 8; nf++)
        #pragma unroll
        for (int r = 0; r < 4; r++) o[nf][r] = 0.f;

    const int n_kt = 2 * qt + 2;
    const int row0 = q0 + mb + grp;
    const int row1 = row0 + 8;

    for (int kt = 0; kt < n_kt; kt++) {
        const int k0 = kt * 64;
        const int buf = kt & 1;
        const bool has_next = (kt + 1 < n_kt);

        __syncthreads();   // all compute on buf^1 (tile kt-1) done before overwrite

        if (has_next) {
            const int k0n = (kt + 1) * 64;
            const int nb = buf ^ 1;
            for (int i = tid; i < 1024; i += 256) {
                int r = i >> 4, c4 = (i & 15) * 4;
                const size_t src = (size_t)(k0n + r) * HD + c4;
                CP16(kBuf[nb] + (uint32_t)((r * KS_STR + c4) * 4), Kg + src);
                CP16(vBuf[nb] + (uint32_t)((r * VS_STR + c4) * 4), Vg + src);
            }
            CP_COMMIT();
            CP_WAIT(1);    // tile kt (and Q) complete; kt+1 in flight
        } else {
            CP_WAIT(0);
        }
        __syncthreads();   // tile kt visible to all threads

        if (k0 <= q0 + mb + 15) {
            // S = Q @ K^T
            float sc[8][4];
            #pragma unroll
            for (int nf = 0; nf < 8; nf++)
                #pragma unroll
                for (int r = 0; r < 4; r++) sc[nf][r] = 0.f;

            const uint32_t kLane = kBuf[buf] + (uint32_t)((krow * KS_STR + kcol) * 4);
            #pragma unroll
            for (int kf = 0; kf < 8; kf++) {
                uint32_t a[4];
                ldsm_x4(a, qLane + (uint32_t)(kf * 32));
                #pragma unroll
                for (int nf2 = 0; nf2 < 8; nf2 += 2) {
                    uint32_t kb[4];
                    ldsm_x4(kb, kLane + (uint32_t)((nf2 * 8 * KS_STR) * 4 + kf * 32));
                    mma_tf32(sc[nf2],     a, kb[0], kb[1]);
                    mma_tf32(sc[nf2 + 1], a, kb[2], kb[3]);
                }
            }

            const bool diag = (kt >= 2 * qt);
            float rm0 = -1e30f, rm1 = -1e30f;
            #pragma unroll
            for (int nf = 0; nf < 8; nf++) {
                int c0 = k0 + nf * 8 + 2 * qq;
                float s0v = sc[nf][0] * 0.125f;
                float s1v = sc[nf][1] * 0.125f;
                float s2v = sc[nf][2] * 0.125f;
                float s3v = sc[nf][3] * 0.125f;
                if (diag) {
                    if (c0     > row0) s0v = -1e30f;
                    if (c0 + 1 > row0) s1v = -1e30f;
                    if (c0     > row1) s2v = -1e30f;
                    if (c0 + 1 > row1) s3v = -1e30f;
                }
                sc[nf][0] = s0v; sc[nf][1] = s1v; sc[nf][2] = s2v; sc[nf][3] = s3v;
                rm0 = fmaxf(rm0, fmaxf(s0v, s1v));
                rm1 = fmaxf(rm1, fmaxf(s2v, s3v));
            }
            #pragma unroll
            for (int off = 1; off <= 2; off <<= 1) {
                rm0 = fmaxf(rm0, __shfl_xor_sync(0xffffffffu, rm0, off));
                rm1 = fmaxf(rm1, __shfl_xor_sync(0xffffffffu, rm1, off));
            }
            float mn0 = fmaxf(m0, rm0);
            float mn1 = fmaxf(m1, rm1);

            float s0 = 0.f, s1 = 0.f;
            #pragma unroll
            for (int nf = 0; nf < 8; nf++) {
                float p0 = __expf(sc[nf][0] - mn0);
                float p1 = __expf(sc[nf][1] - mn0);
                float p2 = __expf(sc[nf][2] - mn1);
                float p3 = __expf(sc[nf][3] - mn1);
                sc[nf][0] = p0; sc[nf][1] = p1; sc[nf][2] = p2; sc[nf][3] = p3;
                s0 += p0 + p1;
                s1 += p2 + p3;
            }
            #pragma unroll
            for (int off = 1; off <= 2; off <<= 1) {
                s0 += __shfl_xor_sync(0xffffffffu, s0, off);
                s1 += __shfl_xor_sync(0xffffffffu, s1, off);
            }
            float a0 = __expf(m0 - mn0);
            float a1 = __expf(m1 - mn1);
            l0 = l0 * a0 + s0;
            l1 = l1 * a1 + s1;
            m0 = mn0; m1 = mn1;
            #pragma unroll
            for (int nf = 0; nf < 8; nf++) {
                o[nf][0] *= a0; o[nf][1] *= a0;
                o[nf][2] *= a1; o[nf][3] *= a1;
            }

            // O += P @ V with permuted k: A-frag = {sc0, sc2, sc1, sc3},
            // B rows 2q, 2q+1.
            const uint32_t* Vb = smu + (vBuf[buf] - sbase) / 4;
            #pragma unroll
            for (int kf = 0; kf < 8; kf++) {
                uint32_t a[4];
                a[0] = f2tf32(sc[kf][0]);
                a[1] = f2tf32(sc[kf][2]);
                a[2] = f2tf32(sc[kf][1]);
                a[3] = f2tf32(sc[kf][3]);
                const int r0 = (kf * 8 + 2 * qq) * VS_STR;
                #pragma unroll
                for (int nf = 0; nf < 8; nf++) {
                    uint32_t b0 = Vb[r0 + nf * 8 + grp];
                    uint32_t b1 = Vb[r0 + VS_STR + nf * 8 + grp];
                    mma_tf32(o[nf], a, b0, b1);
                }
            }
        }
    }

    // finalize; ctx written as tf32 bits for the O-proj GEMM
    float inv0 = 1.f / l0;
    float inv1 = 1.f / l1;
    #pragma unroll
    for (int nf = 0; nf < 8; nf++) {
        int c = h * HD + nf * 8 + 2 * qq;
        *(uint2*)&g_ctx[((size_t)b * SS + row0) * DM + c] =
            make_uint2(f2tf32(o[nf][0] * inv0), f2tf32(o[nf][1] * inv0));
        *(uint2*)&g_ctx[((size_t)b * SS + row1) * DM + c] =
            make_uint2(f2tf32(o[nf][2] * inv1), f2tf32(o[nf][3] * inv1));
    }
}

// ---------------------------------------------------------------------------
extern "C" void kernel_launch(void* const* d_in, const int* in_sizes, int n_in,
                              void* d_out, int out_size)
{
    const float* states = (const float*)d_in[0];
    const float* Wq = (const float*)d_in[1];
    const float* bq = (const float*)d_in[2];
    const float* Wk = (const float*)d_in[3];
    const float* bk = (const float*)d_in[4];
    const float* Wv = (const float*)d_in[5];
    const float* bv = (const float*)d_in[6];
    const float* bo = (const float*)d_in[8];
    float* out = (float*)d_out;

    uint32_t* a32_ptr = nullptr;
    uint32_t* ctx_ptr = nullptr;
    cudaGetSymbolAddress((void**)&a32_ptr, g_a32);
    cudaGetSymbolAddress((void**)&ctx_ptr, g_ctx);

    cudaFuncSetAttribute(gemm_tf32_bias_tanh<0>,
                         cudaFuncAttributeMaxDynamicSharedMemorySize, GEMM_SMEM);
    cudaFuncSetAttribute(gemm_tf32_bias_tanh<1>,
                         cudaFuncAttributeMaxDynamicSharedMemorySize, GEMM_SMEM);
    cudaFuncSetAttribute(flash_attn_tf32,
                         cudaFuncAttributeMaxDynamicSharedMemorySize, SMEM_ATTN2);

    // 0) convert states + weights to tf32 bits
    convert_inputs<<<8192, 256>>>(states, Wq, Wk, Wv, (const float*)d_in[7]);

    // 1) QKV projections (fused over z)
    dim3 gq(DM / 128, MT / 128, 3);
    gemm_tf32_bias_tanh<0><<<gq, 256, GEMM_SMEM>>>(a32_ptr, bq, bk, bv, nullptr);

    // 2) causal flash attention
    dim3 ga(SS / 128, NH, BB);
    flash_attn_tf32<<<ga, 256, SMEM_ATTN2>>>();

    // 3) output projection
    dim3 go(DM / 128, MT / 128, 1);
    gemm_tf32_bias_tanh<1><<<go, 256, GEMM_SMEM>>>(ctx_ptr, bo, nullptr, nullptr, out);
}

// round 11
// speedup vs baseline: 6.2271x; 1.9662x over previous
#include <cuda_runtime.h>
#include <cuda_fp16.h>
#include <math.h>
#include <stdint.h>

#define BB 2
#define SS 2048
#define DM 1024
#define NH 16
#define HD 64
#define MT (BB*SS)   // 4096 rows total

// Scratch (allocation-free), fp16 storage.
__device__ __half g_a16[MT*DM];          // states
__device__ __half g_w16[4*DM*DM];        // Wq|Wk|Wv|Wo
__device__ __half g_q[BB*NH*SS*HD];      // tanh(qkv)
__device__ __half g_k[BB*NH*SS*HD];
__device__ __half g_v[BB*NH*SS*HD];
__device__ __half g_ctx[MT*DM];          // attention out

__device__ __forceinline__ uint32_t smem_u32(const void* p) {
    uint32_t a;
    asm("{ .reg .u64 t; cvta.to.shared.u64 t, %1; cvt.u32.u64 %0, t; }"
        : "=r"(a) : "l"(p));
    return a;
}

__device__ __forceinline__ void mma_f16(float* c, const uint32_t* a,
                                        uint32_t b0, uint32_t b1) {
    asm volatile(
        "mma.sync.aligned.m16n8k16.row.col.f32.f16.f16.f32 "
        "{%0,%1,%2,%3},{%4,%5,%6,%7},{%8,%9},{%0,%1,%2,%3};\n"
        : "+f"(c[0]), "+f"(c[1]), "+f"(c[2]), "+f"(c[3])
        : "r"(a[0]), "r"(a[1]), "r"(a[2]), "r"(a[3]), "r"(b0), "r"(b1));
}

__device__ __forceinline__ void ldsm_x4(uint32_t* r, uint32_t saddr) {
    asm volatile(
        "ldmatrix.sync.aligned.m8n8.x4.shared.b16 {%0,%1,%2,%3}, [%4];"
        : "=r"(r[0]), "=r"(r[1]), "=r"(r[2]), "=r"(r[3])
        : "r"(saddr));
}
__device__ __forceinline__ void ldsm_x4_t(uint32_t* r, uint32_t saddr) {
    asm volatile(
        "ldmatrix.sync.aligned.m8n8.x4.trans.shared.b16 {%0,%1,%2,%3}, [%4];"
        : "=r"(r[0]), "=r"(r[1]), "=r"(r[2]), "=r"(r[3])
        : "r"(saddr));
}

__device__ __forceinline__ uint32_t pack_h2(float lo, float hi) {
    __half2 h = __floats2half2_rn(lo, hi);
    return *reinterpret_cast<uint32_t*>(&h);
}

#define CP16(dst, src) \
    asm volatile("cp.async.cg.shared.global [%0], [%1], 16;" \
                 :: "r"(dst), "l"(src))
#define CP_COMMIT() asm volatile("cp.async.commit_group;" ::: "memory")
#define CP_WAIT(n)  asm volatile("cp.async.wait_group %0;" :: "n"(n) : "memory")

// ---------------------------------------------------------------------------
// Pre-convert: states + 4 weights -> fp16.
// ---------------------------------------------------------------------------
__global__ void __launch_bounds__(256) convert_inputs(
    const float* __restrict__ states,
    const float* __restrict__ Wq, const float* __restrict__ Wk,
    const float* __restrict__ Wv, const float* __restrict__ Wo)
{
    size_t idx = (size_t)blockIdx.x * blockDim.x + threadIdx.x;  // float4 idx
    const float* src;
    __half* dst;
    size_t off;
    if (idx < 1048576) {
        src = states; dst = g_a16; off = idx;
    } else {
        size_t j = idx - 1048576;
        int w = (int)(j >> 18);
        off = j & 262143;
        src = (w == 0) ? Wq : (w == 1) ? Wk : (w == 2) ? Wv : Wo;
        dst = g_w16 + (size_t)w * 1048576;
    }
    float4 v = *(const float4*)(src + off * 4);
    uint2 u = make_uint2(pack_h2(v.x, v.y), pack_h2(v.z, v.w));
    *(uint2*)(dst + off * 4) = u;
}

// ---------------------------------------------------------------------------
// FP16 tensor-core GEMM: C = tanh(A @ W + bias).
// CTA tile 128x128, K-step 32, 4-stage cp.async, 8 warps (2x4) 64x32.
// A frags: ldmatrix.x4 (stride 40 halfs, conflict-free).
// B frags: ldmatrix.x4.trans on [k][n] tile (stride 136 halfs).
// ---------------------------------------------------------------------------
#define ASTR 40
#define BSTR 136
#define STAGES 4
#define A_STG (128 * ASTR)               // halfs (10240 B)
#define B_STG (32 * BSTR)                // halfs (8704 B)
#define GEMM_SMEM (STAGES * (A_STG + B_STG) * 2)   // 75776 B

template<int MODE>
__global__ void __launch_bounds__(256, 2) gemm_f16_bias_tanh(
    const __half* __restrict__ Abase,
    const float* __restrict__ bq, const float* __restrict__ bk,
    const float* __restrict__ bv,
    float* __restrict__ outO)
{
    extern __shared__ __half hsm[];
    __half* smA = hsm;
    __half* smB = hsm + STAGES * A_STG;
    const uint32_t smA_u = smem_u32(smA);
    const uint32_t smB_u = smem_u32(smB);

    const __half* W;
    const float* bias;
    __half* outq;
    if (MODE == 0) {
        int z = blockIdx.z;
        W    = g_w16 + (size_t)z * (DM * DM);
        bias = (z == 0) ? bq : (z == 1) ? bk : bv;
        outq = (z == 0) ? g_q : (z == 1) ? g_k : g_v;
    } else {
        W = g_w16 + (size_t)3 * (DM * DM);
        bias = bq;
        outq = nullptr;
    }

    const int tid  = threadIdx.x;
    const int wid  = tid >> 5;
    const int lane = tid & 31;
    const int grp  = lane >> 2;
    const int q    = lane & 3;
    const int wm   = wid & 1;
    const int wn   = wid >> 1;

    const int bm = blockIdx.y * 128;
    const int bn = blockIdx.x * 128;

    // Staging: A 128x32 halfs = 512 16B-chunks; B 32x128 halfs = 512 chunks.
    const int a_row0 = tid >> 2, a_c = (tid & 3) * 8;
    const int b_r0   = tid >> 4, b_c8 = (tid & 15) * 8;

    const __half* Ap0 = Abase + (size_t)(bm + a_row0) * DM + a_c;
    const __half* Ap1 = Abase + (size_t)(bm + a_row0 + 64) * DM + a_c;
    const __half* Wp0 = W + (size_t)b_r0 * DM + bn + b_c8;
    const __half* Wp1 = W + (size_t)(b_r0 + 16) * DM + bn + b_c8;

    const uint32_t aoff0 = (uint32_t)((a_row0 * ASTR + a_c) * 2);
    const uint32_t aoff1 = (uint32_t)(((a_row0 + 64) * ASTR + a_c) * 2);
    const uint32_t boff0 = (uint32_t)((b_r0 * BSTR + b_c8) * 2);
    const uint32_t boff1 = (uint32_t)(((b_r0 + 16) * BSTR + b_c8) * 2);

    // ldmatrix lane addresses
    const uint32_t aFragOff = (uint32_t)(((wm * 64 + (lane & 15)) * ASTR
                                          + (lane >> 4) * 8) * 2);
    const uint32_t bLaneOff = (uint32_t)(((((lane >> 3) & 1) * 8 + (lane & 7)) * BSTR
                                          + (lane >> 4) * 8) * 2);

    float acc[4][4][4];
    #pragma unroll
    for (int i = 0; i < 4; i++)
        #pragma unroll
        for (int j = 0; j < 4; j++)
            #pragma unroll
            for (int r = 0; r < 4; r++) acc[i][j][r] = 0.f;

    #pragma unroll
    for (int s = 0; s < STAGES - 1; s++) {
        uint32_t aB = smA_u + (uint32_t)(s * A_STG * 2);
        uint32_t bB = smB_u + (uint32_t)(s * B_STG * 2);
        const int k0 = s * 32;
        CP16(aB + aoff0, Ap0 + k0);
        CP16(aB + aoff1, Ap1 + k0);
        CP16(bB + boff0, Wp0 + (size_t)k0 * DM);
        CP16(bB + boff1, Wp1 + (size_t)k0 * DM);
        CP_COMMIT();
    }

    for (int i = 0; i < DM / 32; i++) {
        CP_WAIT(2);
        __syncthreads();

        int pre = i + STAGES - 1;
        if (pre < DM / 32) {
            int s = pre & (STAGES - 1);
            uint32_t aB = smA_u + (uint32_t)(s * A_STG * 2);
            uint32_t bB = smB_u + (uint32_t)(s * B_STG * 2);
            const int k0 = pre * 32;
            CP16(aB + aoff0, Ap0 + k0);
            CP16(aB + aoff1, Ap1 + k0);
            CP16(bB + boff0, Wp0 + (size_t)k0 * DM);
            CP16(bB + boff1, Wp1 + (size_t)k0 * DM);
        }
        CP_COMMIT();

        const int st = i & (STAGES - 1);
        const uint32_t aAddr = smA_u + (uint32_t)(st * A_STG * 2) + aFragOff;
        const uint32_t bAddr = smB_u + (uint32_t)(st * B_STG * 2) + bLaneOff;
        #pragma unroll
        for (int kk = 0; kk < 32; kk += 16) {
            uint32_t af[4][4];
            #pragma unroll
            for (int im = 0; im < 4; im++)
                ldsm_x4(af[im], aAddr + (uint32_t)((im * 16 * ASTR + kk) * 2));
            uint32_t bf[2][4];   // [half16][4 regs = b0/b1 for 2 n-blocks]
            #pragma unroll
            for (int hh = 0; hh < 2; hh++)
                ldsm_x4_t(bf[hh], bAddr + (uint32_t)((kk * BSTR
                                   + wn * 32 + hh * 16) * 2));
            #pragma unroll
            for (int im = 0; im < 4; im++) {
                mma_f16(acc[im][0], af[im], bf[0][0], bf[0][1]);
                mma_f16(acc[im][1], af[im], bf[0][2], bf[0][3]);
                mma_f16(acc[im][2], af[im], bf[1][0], bf[1][1]);
                mma_f16(acc[im][3], af[im], bf[1][2], bf[1][3]);
            }
        }
    }

    #pragma unroll
    for (int im = 0; im < 4; im++) {
        #pragma unroll
        for (int in_ = 0; in_ < 4; in_++) {
            int n0 = bn + wn * 32 + in_ * 8 + 2 * q;
            float b0v = bias[n0], b1v = bias[n0 + 1];
            #pragma unroll
            for (int half = 0; half < 2; half++) {
                int m = bm + wm * 64 + im * 16 + grp + half * 8;
                float y0 = tanhf(acc[im][in_][half * 2 + 0] + b0v);
                float y1 = tanhf(acc[im][in_][half * 2 + 1] + b1v);
                if (MODE == 0) {
                    int bbi = m >> 11;
                    int s   = m & 2047;
                    int h0  = n0 >> 6;
                    int d0  = n0 & 63;
                    size_t base = (((size_t)bbi * NH + h0) * SS + s) * HD + d0;
                    *reinterpret_cast<__half2*>(&outq[base]) =
                        __floats2half2_rn(y0, y1);
                } else {
                    outO[(size_t)m * DM + n0]     = y0;
                    outO[(size_t)m * DM + n0 + 1] = y1;
                }
            }
        }
    }
}

// ---------------------------------------------------------------------------
// FP16 causal flash attention. Double-buffered K/V via cp.async.
// S = Q@K^T with m16n8k16 (K natural layout = B via plain ldsm).
// P packs directly from the S C-fragment into the A-fragment (half2).
// V B-frags via ldmatrix.trans. Smem = Q + 2(K+V) = 54KB -> 2 CTAs/SM.
// ---------------------------------------------------------------------------
#define QSTR 72
#define KSTR 72
#define VSTR 72
#define Q_H (128 * QSTR)
#define K_H (64 * KSTR)
#define V_H (64 * VSTR)
#define SMEM_ATTN ((Q_H + 2*K_H + 2*V_H) * 2)

__global__ void __launch_bounds__(256, 2) flash_attn_f16()
{
    extern __shared__ __half smh[];

    const int tid  = threadIdx.x;
    const int wid  = tid >> 5;
    const int lane = tid & 31;
    const int grp  = lane >> 2;
    const int qq   = lane & 3;
    const int qt   = (gridDim.x - 1) - blockIdx.x;
    const int h    = blockIdx.y;
    const int b    = blockIdx.z;
    const int q0   = qt * 128;
    const int mb   = wid * 16;

    const size_t head_off = ((size_t)(b * NH + h)) * SS * HD;
    const __half* Qg = g_q + head_off;
    const __half* Kg = g_k + head_off;
    const __half* Vg = g_v + head_off;

    const uint32_t sbase = smem_u32(smh);
    const uint32_t kBuf[2] = { sbase + Q_H * 2, sbase + (Q_H + K_H) * 2 };
    const uint32_t vBuf[2] = { sbase + (Q_H + 2 * K_H) * 2,
                               sbase + (Q_H + 2 * K_H + V_H) * 2 };

    // lane offsets
    const uint32_t qLane = sbase + (uint32_t)(((mb + (lane & 15)) * QSTR
                                               + (lane >> 4) * 8) * 2);
    const uint32_t kLaneOff = (uint32_t)(((((lane >> 4) & 1) * 8 + (lane & 7)) * KSTR
                                          + ((lane >> 3) & 1) * 8) * 2);
    const uint32_t vLaneOff = (uint32_t)(((((lane >> 3) & 1) * 8 + (lane & 7)) * VSTR
                                          + (lane >> 4) * 8) * 2);

    // Q tile (1024 chunks)
    for (int i = tid; i < 1024; i += 256) {
        int r = i >> 3, c8 = (i & 7) * 8;
        CP16(sbase + (uint32_t)((r * QSTR + c8) * 2),
             Qg + (size_t)(q0 + r) * HD + c8);
    }
    CP_COMMIT();

    // K/V tile 0
    for (int i = tid; i < 512; i += 256) {
        int r = i >> 3, c8 = (i & 7) * 8;
        const size_t src = (size_t)r * HD + c8;
        CP16(kBuf[0] + (uint32_t)((r * KSTR + c8) * 2), Kg + src);
        CP16(vBuf[0] + (uint32_t)((r * VSTR + c8) * 2), Vg + src);
    }
    CP_COMMIT();

    float m0 = -1e30f, m1 = -1e30f, l0 = 0.f, l1 = 0.f;
    float o[8][4];
    #pragma unroll
    for (int nf = 0; nf < 8; nf++)
        #pragma unroll
        for (int r = 0; r < 4; r++) o[nf][r] = 0.f;

    const int n_kt = 2 * qt + 2;
    const int row0 = q0 + mb + grp;
    const int row1 = row0 + 8;

    for (int kt = 0; kt < n_kt; kt++) {
        const int k0 = kt * 64;
        const int buf = kt & 1;
        const bool has_next = (kt + 1 < n_kt);

        __syncthreads();

        if (has_next) {
            const int k0n = (kt + 1) * 64;
            const int nb = buf ^ 1;
            for (int i = tid; i < 512; i += 256) {
                int r = i >> 3, c8 = (i & 7) * 8;
                const size_t src = (size_t)(k0n + r) * HD + c8;
                CP16(kBuf[nb] + (uint32_t)((r * KSTR + c8) * 2), Kg + src);
                CP16(vBuf[nb] + (uint32_t)((r * VSTR + c8) * 2), Vg + src);
            }
            CP_COMMIT();
            CP_WAIT(1);
        } else {
            CP_WAIT(0);
        }
        __syncthreads();

        if (k0 <= q0 + mb + 15) {
            // S = Q @ K^T (per-warp 16 x 64)
            float sc[8][4];
            #pragma unroll
            for (int nf = 0; nf < 8; nf++)
                #pragma unroll
                for (int r = 0; r < 4; r++) sc[nf][r] = 0.f;

            const uint32_t kLane = kBuf[buf] + kLaneOff;
            #pragma unroll
            for (int kf = 0; kf < 4; kf++) {
                uint32_t a[4];
                ldsm_x4(a, qLane + (uint32_t)(kf * 32));
                #pragma unroll
                for (int nf2 = 0; nf2 < 8; nf2 += 2) {
                    uint32_t kb[4];
                    // non-trans ldsm on K[seq][d]: B frags for 2 n-blocks
                    ldsm_x4(kb, kLane + (uint32_t)((nf2 * 8 * KSTR) * 2 + kf * 32));
                    mma_f16(sc[nf2],     a, kb[0], kb[1]);
                    mma_f16(sc[nf2 + 1], a, kb[2], kb[3]);
                }
            }

            const bool diag = (kt >= 2 * qt);
            float rm0 = -1e30f, rm1 = -1e30f;
            #pragma unroll
            for (int nf = 0; nf < 8; nf++) {
                int c0 = k0 + nf * 8 + 2 * qq;
                float s0v = sc[nf][0] * 0.125f;
                float s1v = sc[nf][1] * 0.125f;
                float s2v = sc[nf][2] * 0.125f;
                float s3v = sc[nf][3] * 0.125f;
                if (diag) {
                    if (c0     > row0) s0v = -1e30f;
                    if (c0 + 1 > row0) s1v = -1e30f;
                    if (c0     > row1) s2v = -1e30f;
                    if (c0 + 1 > row1) s3v = -1e30f;
                }
                sc[nf][0] = s0v; sc[nf][1] = s1v; sc[nf][2] = s2v; sc[nf][3] = s3v;
                rm0 = fmaxf(rm0, fmaxf(s0v, s1v));
                rm1 = fmaxf(rm1, fmaxf(s2v, s3v));
            }
            #pragma unroll
            for (int off = 1; off <= 2; off <<= 1) {
                rm0 = fmaxf(rm0, __shfl_xor_sync(0xffffffffu, rm0, off));
                rm1 = fmaxf(rm1, __shfl_xor_sync(0xffffffffu, rm1, off));
            }
            float mn0 = fmaxf(m0, rm0);
            float mn1 = fmaxf(m1, rm1);

            float s0 = 0.f, s1 = 0.f;
            #pragma unroll
            for (int nf = 0; nf < 8; nf++) {
                float p0 = __expf(sc[nf][0] - mn0);
                float p1 = __expf(sc[nf][1] - mn0);
                float p2 = __expf(sc[nf][2] - mn1);
                float p3 = __expf(sc[nf][3] - mn1);
                sc[nf][0] = p0; sc[nf][1] = p1; sc[nf][2] = p2; sc[nf][3] = p3;
                s0 += p0 + p1;
                s1 += p2 + p3;
            }
            #pragma unroll
            for (int off = 1; off <= 2; off <<= 1) {
                s0 += __shfl_xor_sync(0xffffffffu, s0, off);
                s1 += __shfl_xor_sync(0xffffffffu, s1, off);
            }
            float a0 = __expf(m0 - mn0);
            float a1 = __expf(m1 - mn1);
            l0 = l0 * a0 + s0;
            l1 = l1 * a1 + s1;
            m0 = mn0; m1 = mn1;
            #pragma unroll
            for (int nf = 0; nf < 8; nf++) {
                o[nf][0] *= a0; o[nf][1] *= a0;
                o[nf][2] *= a1; o[nf][3] *= a1;
            }

            // O += P @ V: A-frag packs straight from the S C-fragment.
            const uint32_t vLane = vBuf[buf] + vLaneOff;
            #pragma unroll
            for (int kf = 0; kf < 4; kf++) {
                uint32_t a[4];
                a[0] = pack_h2(sc[2*kf][0],   sc[2*kf][1]);
                a[1] = pack_h2(sc[2*kf][2],   sc[2*kf][3]);
                a[2] = pack_h2(sc[2*kf+1][0], sc[2*kf+1][1]);
                a[3] = pack_h2(sc[2*kf+1][2], sc[2*kf+1][3]);
                #pragma unroll
                for (int nf2 = 0; nf2 < 8; nf2 += 2) {
                    uint32_t vb[4];
                    ldsm_x4_t(vb, vLane + (uint32_t)((kf * 16 * VSTR + nf2 * 8) * 2));
                    mma_f16(o[nf2],     a, vb[0], vb[1]);
                    mma_f16(o[nf2 + 1], a, vb[2], vb[3]);
                }
            }
        }
    }

    float inv0 = 1.f / l0;
    float inv1 = 1.f / l1;
    #pragma unroll
    for (int nf = 0; nf < 8; nf++) {
        int c = h * HD + nf * 8 + 2 * qq;
        *reinterpret_cast<__half2*>(&g_ctx[((size_t)b * SS + row0) * DM + c]) =
            __floats2half2_rn(o[nf][0] * inv0, o[nf][1] * inv0);
        *reinterpret_cast<__half2*>(&g_ctx[((size_t)b * SS + row1) * DM + c]) =
            __floats2half2_rn(o[nf][2] * inv1, o[nf][3] * inv1);
    }
}

// ---------------------------------------------------------------------------
extern "C" void kernel_launch(void* const* d_in, const int* in_sizes, int n_in,
                              void* d_out, int out_size)
{
    const float* states = (const float*)d_in[0];
    const float* Wq = (const float*)d_in[1];
    const float* bq = (const float*)d_in[2];
    const float* Wk = (const float*)d_in[3];
    const float* bk = (const float*)d_in[4];
    const float* Wv = (const float*)d_in[5];
    const float* bv = (const float*)d_in[6];
    const float* bo = (const float*)d_in[8];
    float* out = (float*)d_out;

    __half* a16_ptr = nullptr;
    __half* ctx_ptr = nullptr;
    cudaGetSymbolAddress((void**)&a16_ptr, g_a16);
    cudaGetSymbolAddress((void**)&ctx_ptr, g_ctx);

    cudaFuncSetAttribute(gemm_f16_bias_tanh<0>,
                         cudaFuncAttributeMaxDynamicSharedMemorySize, GEMM_SMEM);
    cudaFuncSetAttribute(gemm_f16_bias_tanh<1>,
                         cudaFuncAttributeMaxDynamicSharedMemorySize, GEMM_SMEM);
    cudaFuncSetAttribute(flash_attn_f16,
                         cudaFuncAttributeMaxDynamicSharedMemorySize, SMEM_ATTN);

    // 0) convert inputs to fp16
    convert_inputs<<<8192, 256>>>(states, Wq, Wk, Wv, (const float*)d_in[7]);

    // 1) QKV projections
    dim3 gq(DM / 128, MT / 128, 3);
    gemm_f16_bias_tanh<0><<<gq, 256, GEMM_SMEM>>>(a16_ptr, bq, bk, bv, nullptr);

    // 2) causal flash attention
    dim3 ga(SS / 128, NH, BB);
    flash_attn_f16<<<ga, 256, SMEM_ATTN>>>();

    // 3) output projection
    dim3 go(DM / 128, MT / 128, 1);
    gemm_f16_bias_tanh<1><<<go, 256, GEMM_SMEM>>>(ctx_ptr, bo, nullptr, nullptr, out);
}

// round 12
// speedup vs baseline: 6.2387x; 1.0019x over previous
#include <cuda_runtime.h>
#include <cuda_fp16.h>
#include <math.h>
#include <stdint.h>

#define BB 2
#define SS 2048
#define DM 1024
#define NH 16
#define HD 64
#define MT (BB*SS)   // 4096 rows total

// Scratch (allocation-free), fp16 storage.
__device__ __half g_a16[MT*DM];          // states
__device__ __half g_w16[4*DM*DM];        // Wq|Wk|Wv|Wo
__device__ __half g_q[BB*NH*SS*HD];      // tanh(qkv)
__device__ __half g_k[BB*NH*SS*HD];
__device__ __half g_v[BB*NH*SS*HD];
__device__ __half g_ctx[MT*DM];          // attention out

__device__ __forceinline__ uint32_t smem_u32(const void* p) {
    uint32_t a;
    asm("{ .reg .u64 t; cvta.to.shared.u64 t, %1; cvt.u32.u64 %0, t; }"
        : "=r"(a) : "l"(p));
    return a;
}

__device__ __forceinline__ void mma_f16(float* c, const uint32_t* a,
                                        uint32_t b0, uint32_t b1) {
    asm volatile(
        "mma.sync.aligned.m16n8k16.row.col.f32.f16.f16.f32 "
        "{%0,%1,%2,%3},{%4,%5,%6,%7},{%8,%9},{%0,%1,%2,%3};\n"
        : "+f"(c[0]), "+f"(c[1]), "+f"(c[2]), "+f"(c[3])
        : "r"(a[0]), "r"(a[1]), "r"(a[2]), "r"(a[3]), "r"(b0), "r"(b1));
}

__device__ __forceinline__ void ldsm_x4(uint32_t* r, uint32_t saddr) {
    asm volatile(
        "ldmatrix.sync.aligned.m8n8.x4.shared.b16 {%0,%1,%2,%3}, [%4];"
        : "=r"(r[0]), "=r"(r[1]), "=r"(r[2]), "=r"(r[3])
        : "r"(saddr));
}
__device__ __forceinline__ void ldsm_x4_t(uint32_t* r, uint32_t saddr) {
    asm volatile(
        "ldmatrix.sync.aligned.m8n8.x4.trans.shared.b16 {%0,%1,%2,%3}, [%4];"
        : "=r"(r[0]), "=r"(r[1]), "=r"(r[2]), "=r"(r[3])
        : "r"(saddr));
}

__device__ __forceinline__ uint32_t pack_h2(float lo, float hi) {
    __half2 h = __floats2half2_rn(lo, hi);
    return *reinterpret_cast<uint32_t*>(&h);
}

#define CP16(dst, src) \
    asm volatile("cp.async.cg.shared.global [%0], [%1], 16;" \
                 :: "r"(dst), "l"(src))
#define CP_COMMIT() asm volatile("cp.async.commit_group;" ::: "memory")
#define CP_WAIT(n)  asm volatile("cp.async.wait_group %0;" :: "n"(n) : "memory")

// ---------------------------------------------------------------------------
// Pre-convert: states + 4 weights -> fp16.
// ---------------------------------------------------------------------------
__global__ void __launch_bounds__(256) convert_inputs(
    const float* __restrict__ states,
    const float* __restrict__ Wq, const float* __restrict__ Wk,
    const float* __restrict__ Wv, const float* __restrict__ Wo)
{
    size_t idx = (size_t)blockIdx.x * blockDim.x + threadIdx.x;  // float4 idx
    const float* src;
    __half* dst;
    size_t off;
    if (idx < 1048576) {
        src = states; dst = g_a16; off = idx;
    } else {
        size_t j = idx - 1048576;
        int w = (int)(j >> 18);
        off = j & 262143;
        src = (w == 0) ? Wq : (w == 1) ? Wk : (w == 2) ? Wv : Wo;
        dst = g_w16 + (size_t)w * 1048576;
    }
    float4 v = *(const float4*)(src + off * 4);
    uint2 u = make_uint2(pack_h2(v.x, v.y), pack_h2(v.z, v.w));
    *(uint2*)(dst + off * 4) = u;
}

// ---------------------------------------------------------------------------
// FP16 tensor-core GEMM: C = tanh(A @ W + bias).
// CTA tile 128x128, K-step 64, 3-stage cp.async, 8 warps (2x4) 64x32.
// A frags: ldmatrix.x4 (stride 72 halfs = 16B phase mod 128, conflict-free).
// B frags: ldmatrix.x4.trans on [k][n] tile (stride 136 halfs).
// ---------------------------------------------------------------------------
#define ASTR 72
#define BSTR 136
#define STAGES 3
#define KSTEP 64
#define A_STG (128 * ASTR)               // halfs (18432 B)
#define B_STG (KSTEP * BSTR)             // halfs (17408 B)
#define GEMM_SMEM (STAGES * (A_STG + B_STG) * 2)   // 107520 B

template<int MODE>
__global__ void __launch_bounds__(256, 2) gemm_f16_bias_tanh(
    const __half* __restrict__ Abase,
    const float* __restrict__ bq, const float* __restrict__ bk,
    const float* __restrict__ bv,
    float* __restrict__ outO)
{
    extern __shared__ __half hsm[];
    const uint32_t smA_u = smem_u32(hsm);
    const uint32_t smB_u = smA_u + STAGES * A_STG * 2;

    const __half* W;
    const float* bias;
    __half* outq;
    if (MODE == 0) {
        int z = blockIdx.z;
        W    = g_w16 + (size_t)z * (DM * DM);
        bias = (z == 0) ? bq : (z == 1) ? bk : bv;
        outq = (z == 0) ? g_q : (z == 1) ? g_k : g_v;
    } else {
        W = g_w16 + (size_t)3 * (DM * DM);
        bias = bq;
        outq = nullptr;
    }

    const int tid  = threadIdx.x;
    const int wid  = tid >> 5;
    const int lane = tid & 31;
    const int grp  = lane >> 2;
    const int q    = lane & 3;
    const int wm   = wid & 1;
    const int wn   = wid >> 1;

    const int bm = blockIdx.y * 128;
    const int bn = blockIdx.x * 128;

    // Staging: A 128x64 halfs = 1024 chunks; B 64x128 halfs = 1024 chunks.
    // 4 chunks each per thread per tile.
    const __half* aPtr[4];
    const __half* bPtr[4];
    uint32_t aSm[4], bSm[4];
    #pragma unroll
    for (int it = 0; it < 4; it++) {
        int c = tid + 256 * it;
        int ar = c >> 3, ac8 = (c & 7) * 8;          // A: 128 rows x 8 chunks
        aPtr[it] = Abase + (size_t)(bm + ar) * DM + ac8;
        aSm[it]  = (uint32_t)((ar * ASTR + ac8) * 2);
        int br = c >> 4, bc8 = (c & 15) * 8;          // B: 64 rows x 16 chunks
        bPtr[it] = W + (size_t)br * DM + bn + bc8;
        bSm[it]  = (uint32_t)((br * BSTR + bc8) * 2);
    }

    // ldmatrix lane addresses
    const uint32_t aFragOff = (uint32_t)(((wm * 64 + (lane & 15)) * ASTR
                                          + (lane >> 4) * 8) * 2);
    const uint32_t bLaneOff = (uint32_t)(((((lane >> 3) & 1) * 8 + (lane & 7)) * BSTR
                                          + (lane >> 4) * 8) * 2);

    float acc[4][4][4];
    #pragma unroll
    for (int i = 0; i < 4; i++)
        #pragma unroll
        for (int j = 0; j < 4; j++)
            #pragma unroll
            for (int r = 0; r < 4; r++) acc[i][j][r] = 0.f;

    // Prologue: stages 0,1
    #pragma unroll
    for (int s = 0; s < STAGES - 1; s++) {
        const int k0 = s * KSTEP;
        uint32_t aB = smA_u + (uint32_t)(s * A_STG * 2);
        uint32_t bB = smB_u + (uint32_t)(s * B_STG * 2);
        #pragma unroll
        for (int it = 0; it < 4; it++) {
            CP16(aB + aSm[it], aPtr[it] + k0);
            CP16(bB + bSm[it], bPtr[it] + (size_t)k0 * DM);
        }
        CP_COMMIT();
    }

    const int NITER = DM / KSTEP;   // 16
    for (int i = 0; i < NITER; i++) {
        CP_WAIT(1);
        __syncthreads();

        int pre = i + STAGES - 1;
        if (pre < NITER) {
            int s = pre % STAGES;
            const int k0 = pre * KSTEP;
            uint32_t aB = smA_u + (uint32_t)(s * A_STG * 2);
            uint32_t bB = smB_u + (uint32_t)(s * B_STG * 2);
            #pragma unroll
            for (int it = 0; it < 4; it++) {
                CP16(aB + aSm[it], aPtr[it] + k0);
                CP16(bB + bSm[it], bPtr[it] + (size_t)k0 * DM);
            }
        }
        CP_COMMIT();

        const int st = i % STAGES;
        const uint32_t aAddr = smA_u + (uint32_t)(st * A_STG * 2) + aFragOff;
        const uint32_t bAddr = smB_u + (uint32_t)(st * B_STG * 2) + bLaneOff;
        #pragma unroll
        for (int kk = 0; kk < KSTEP; kk += 16) {
            uint32_t af[4][4];
            #pragma unroll
            for (int im = 0; im < 4; im++)
                ldsm_x4(af[im], aAddr + (uint32_t)((im * 16 * ASTR + kk) * 2));
            uint32_t bf[2][4];
            #pragma unroll
            for (int hh = 0; hh < 2; hh++)
                ldsm_x4_t(bf[hh], bAddr + (uint32_t)((kk * BSTR
                                   + wn * 32 + hh * 16) * 2));
            #pragma unroll
            for (int im = 0; im < 4; im++) {
                mma_f16(acc[im][0], af[im], bf[0][0], bf[0][1]);
                mma_f16(acc[im][1], af[im], bf[0][2], bf[0][3]);
                mma_f16(acc[im][2], af[im], bf[1][0], bf[1][1]);
                mma_f16(acc[im][3], af[im], bf[1][2], bf[1][3]);
            }
        }
    }

    #pragma unroll
    for (int im = 0; im < 4; im++) {
        #pragma unroll
        for (int in_ = 0; in_ < 4; in_++) {
            int n0 = bn + wn * 32 + in_ * 8 + 2 * q;
            float b0v = bias[n0], b1v = bias[n0 + 1];
            #pragma unroll
            for (int half = 0; half < 2; half++) {
                int m = bm + wm * 64 + im * 16 + grp + half * 8;
                float y0 = tanhf(acc[im][in_][half * 2 + 0] + b0v);
                float y1 = tanhf(acc[im][in_][half * 2 + 1] + b1v);
                if (MODE == 0) {
                    int bbi = m >> 11;
                    int s   = m & 2047;
                    int h0  = n0 >> 6;
                    int d0  = n0 & 63;
                    size_t base = (((size_t)bbi * NH + h0) * SS + s) * HD + d0;
                    *reinterpret_cast<__half2*>(&outq[base]) =
                        __floats2half2_rn(y0, y1);
                } else {
                    outO[(size_t)m * DM + n0]     = y0;
                    outO[(size_t)m * DM + n0 + 1] = y1;
                }
            }
        }
    }
}

// ---------------------------------------------------------------------------
// FP16 causal flash attention. Double-buffered 128-row K/V tiles via
// cp.async; each tile computed as two 64-row halves between ONE sync pair.
// S = Q@K^T m16n8k16; P packs from S C-frag; V frags via ldmatrix.trans.
// Smem = Q[128] + 2x(K[128]+V[128]) @ stride 72 = 90KB -> 2 CTAs/SM.
// ---------------------------------------------------------------------------
#define QSTR 72
#define KVSTR 72
#define Q_H (128 * QSTR)
#define KV_H (128 * KVSTR)
#define SMEM_ATTN ((Q_H + 4 * KV_H) * 2)

__global__ void __launch_bounds__(256, 2) flash_attn_f16()
{
    extern __shared__ __half smh[];

    const int tid  = threadIdx.x;
    const int wid  = tid >> 5;
    const int lane = tid & 31;
    const int grp  = lane >> 2;
    const int qq   = lane & 3;
    const int qt   = (gridDim.x - 1) - blockIdx.x;
    const int h    = blockIdx.y;
    const int b    = blockIdx.z;
    const int q0   = qt * 128;
    const int mb   = wid * 16;

    const size_t head_off = ((size_t)(b * NH + h)) * SS * HD;
    const __half* Qg = g_q + head_off;
    const __half* Kg = g_k + head_off;
    const __half* Vg = g_v + head_off;

    const uint32_t sbase = smem_u32(smh);
    const uint32_t kBuf[2] = { sbase + Q_H * 2, sbase + (Q_H + KV_H) * 2 };
    const uint32_t vBuf[2] = { sbase + (Q_H + 2 * KV_H) * 2,
                               sbase + (Q_H + 3 * KV_H) * 2 };

    const uint32_t qLane = sbase + (uint32_t)(((mb + (lane & 15)) * QSTR
                                               + (lane >> 4) * 8) * 2);
    const uint32_t kLaneOff = (uint32_t)(((((lane >> 4) & 1) * 8 + (lane & 7)) * KVSTR
                                          + ((lane >> 3) & 1) * 8) * 2);
    const uint32_t vLaneOff = (uint32_t)(((((lane >> 3) & 1) * 8 + (lane & 7)) * KVSTR
                                          + (lane >> 4) * 8) * 2);

    // Q tile (1024 chunks)
    for (int i = tid; i < 1024; i += 256) {
        int r = i >> 3, c8 = (i & 7) * 8;
        CP16(sbase + (uint32_t)((r * QSTR + c8) * 2),
             Qg + (size_t)(q0 + r) * HD + c8);
    }
    CP_COMMIT();

    // K/V tile 0 (128 rows)
    for (int i = tid; i < 1024; i += 256) {
        int r = i >> 3, c8 = (i & 7) * 8;
        const size_t src = (size_t)r * HD + c8;
        CP16(kBuf[0] + (uint32_t)((r * KVSTR + c8) * 2), Kg + src);
        CP16(vBuf[0] + (uint32_t)((r * KVSTR + c8) * 2), Vg + src);
    }
    CP_COMMIT();

    float m0 = -1e30f, m1 = -1e30f, l0 = 0.f, l1 = 0.f;
    float o[8][4];
    #pragma unroll
    for (int nf = 0; nf < 8; nf++)
        #pragma unroll
        for (int r = 0; r < 4; r++) o[nf][r] = 0.f;

    const int n_kt = qt + 1;            // 128-row K tiles
    const int row0 = q0 + mb + grp;
    const int row1 = row0 + 8;

    for (int kt = 0; kt < n_kt; kt++) {
        const int buf = kt & 1;
        const bool has_next = (kt + 1 < n_kt);

        __syncthreads();

        if (has_next) {
            const int r0n = (kt + 1) * 128;
            const int nb = buf ^ 1;
            for (int i = tid; i < 1024; i += 256) {
                int r = i >> 3, c8 = (i & 7) * 8;
                const size_t src = (size_t)(r0n + r) * HD + c8;
                CP16(kBuf[nb] + (uint32_t)((r * KVSTR + c8) * 2), Kg + src);
                CP16(vBuf[nb] + (uint32_t)((r * KVSTR + c8) * 2), Vg + src);
            }
            CP_COMMIT();
            CP_WAIT(1);
        } else {
            CP_WAIT(0);
        }
        __syncthreads();

        #pragma unroll
        for (int hi = 0; hi < 2; hi++) {
            const int k0h = kt * 128 + hi * 64;
            if (k0h > q0 + mb + 15) continue;   // fully above diagonal

            // S = Q @ K^T (per-warp 16 x 64)
            float sc[8][4];
            #pragma unroll
            for (int nf = 0; nf < 8; nf++)
                #pragma unroll
                for (int r = 0; r < 4; r++) sc[nf][r] = 0.f;

            const uint32_t kLane = kBuf[buf] + (uint32_t)(hi * 64 * KVSTR * 2)
                                 + kLaneOff;
            #pragma unroll
            for (int kf = 0; kf < 4; kf++) {
                uint32_t a[4];
                ldsm_x4(a, qLane + (uint32_t)(kf * 32));
                #pragma unroll
                for (int nf2 = 0; nf2 < 8; nf2 += 2) {
                    uint32_t kb[4];
                    ldsm_x4(kb, kLane + (uint32_t)((nf2 * 8 * KVSTR) * 2 + kf * 32));
                    mma_f16(sc[nf2],     a, kb[0], kb[1]);
                    mma_f16(sc[nf2 + 1], a, kb[2], kb[3]);
                }
            }

            const bool diag = (k0h + 63 > q0 + mb);
            float rm0 = -1e30f, rm1 = -1e30f;
            #pragma unroll
            for (int nf = 0; nf < 8; nf++) {
                int c0 = k0h + nf * 8 + 2 * qq;
                float s0v = sc[nf][0] * 0.125f;
                float s1v = sc[nf][1] * 0.125f;
                float s2v = sc[nf][2] * 0.125f;
                float s3v = sc[nf][3] * 0.125f;
                if (diag) {
                    if (c0     > row0) s0v = -1e30f;
                    if (c0 + 1 > row0) s1v = -1e30f;
                    if (c0     > row1) s2v = -1e30f;
                    if (c0 + 1 > row1) s3v = -1e30f;
                }
                sc[nf][0] = s0v; sc[nf][1] = s1v; sc[nf][2] = s2v; sc[nf][3] = s3v;
                rm0 = fmaxf(rm0, fmaxf(s0v, s1v));
                rm1 = fmaxf(rm1, fmaxf(s2v, s3v));
            }
            #pragma unroll
            for (int off = 1; off <= 2; off <<= 1) {
                rm0 = fmaxf(rm0, __shfl_xor_sync(0xffffffffu, rm0, off));
                rm1 = fmaxf(rm1, __shfl_xor_sync(0xffffffffu, rm1, off));
            }
            float mn0 = fmaxf(m0, rm0);
            float mn1 = fmaxf(m1, rm1);

            float s0 = 0.f, s1 = 0.f;
            #pragma unroll
            for (int nf = 0; nf < 8; nf++) {
                float p0 = __expf(sc[nf][0] - mn0);
                float p1 = __expf(sc[nf][1] - mn0);
                float p2 = __expf(sc[nf][2] - mn1);
                float p3 = __expf(sc[nf][3] - mn1);
                sc[nf][0] = p0; sc[nf][1] = p1; sc[nf][2] = p2; sc[nf][3] = p3;
                s0 += p0 + p1;
                s1 += p2 + p3;
            }
            #pragma unroll
            for (int off = 1; off <= 2; off <<= 1) {
                s0 += __shfl_xor_sync(0xffffffffu, s0, off);
                s1 += __shfl_xor_sync(0xffffffffu, s1, off);
            }
            float a0 = __expf(m0 - mn0);
            float a1 = __expf(m1 - mn1);
            l0 = l0 * a0 + s0;
            l1 = l1 * a1 + s1;
            m0 = mn0; m1 = mn1;
            #pragma unroll
            for (int nf = 0; nf < 8; nf++) {
                o[nf][0] *= a0; o[nf][1] *= a0;
                o[nf][2] *= a1; o[nf][3] *= a1;
            }

            // O += P @ V
            const uint32_t vLane = vBuf[buf] + (uint32_t)(hi * 64 * KVSTR * 2)
                                 + vLaneOff;
            #pragma unroll
            for (int kf = 0; kf < 4; kf++) {
                uint32_t a[4];
                a[0] = pack_h2(sc[2*kf][0],   sc[2*kf][1]);
                a[1] = pack_h2(sc[2*kf][2],   sc[2*kf][3]);
                a[2] = pack_h2(sc[2*kf+1][0], sc[2*kf+1][1]);
                a[3] = pack_h2(sc[2*kf+1][2], sc[2*kf+1][3]);
                #pragma unroll
                for (int nf2 = 0; nf2 < 8; nf2 += 2) {
                    uint32_t vb[4];
                    ldsm_x4_t(vb, vLane + (uint32_t)((kf * 16 * KVSTR + nf2 * 8) * 2));
                    mma_f16(o[nf2],     a, vb[0], vb[1]);
                    mma_f16(o[nf2 + 1], a, vb[2], vb[3]);
                }
            }
        }
    }

    float inv0 = 1.f / l0;
    float inv1 = 1.f / l1;
    #pragma unroll
    for (int nf = 0; nf < 8; nf++) {
        int c = h * HD + nf * 8 + 2 * qq;
        *reinterpret_cast<__half2*>(&g_ctx[((size_t)b * SS + row0) * DM + c]) =
            __floats2half2_rn(o[nf][0] * inv0, o[nf][1] * inv0);
        *reinterpret_cast<__half2*>(&g_ctx[((size_t)b * SS + row1) * DM + c]) =
            __floats2half2_rn(o[nf][2] * inv1, o[nf][3] * inv1);
    }
}

// ---------------------------------------------------------------------------
extern "C" void kernel_launch(void* const* d_in, const int* in_sizes, int n_in,
                              void* d_out, int out_size)
{
    const float* states = (const float*)d_in[0];
    const float* Wq = (const float*)d_in[1];
    const float* bq = (const float*)d_in[2];
    const float* Wk = (const float*)d_in[3];
    const float* bk = (const float*)d_in[4];
    const float* Wv = (const float*)d_in[5];
    const float* bv = (const float*)d_in[6];
    const float* bo = (const float*)d_in[8];
    float* out = (float*)d_out;

    __half* a16_ptr = nullptr;
    __half* ctx_ptr = nullptr;
    cudaGetSymbolAddress((void**)&a16_ptr, g_a16);
    cudaGetSymbolAddress((void**)&ctx_ptr, g_ctx);

    cudaFuncSetAttribute(gemm_f16_bias_tanh<0>,
                         cudaFuncAttributeMaxDynamicSharedMemorySize, GEMM_SMEM);
    cudaFuncSetAttribute(gemm_f16_bias_tanh<1>,
                         cudaFuncAttributeMaxDynamicSharedMemorySize, GEMM_SMEM);
    cudaFuncSetAttribute(flash_attn_f16,
                         cudaFuncAttributeMaxDynamicSharedMemorySize, SMEM_ATTN);

    // 0) convert inputs to fp16
    convert_inputs<<<8192, 256>>>(states, Wq, Wk, Wv, (const float*)d_in[7]);

    // 1) QKV projections
    dim3 gq(DM / 128, MT / 128, 3);
    gemm_f16_bias_tanh<0><<<gq, 256, GEMM_SMEM>>>(a16_ptr, bq, bk, bv, nullptr);

    // 2) causal flash attention
    dim3 ga(SS / 128, NH, BB);
    flash_attn_f16<<<ga, 256, SMEM_ATTN>>>();

    // 3) output projection
    dim3 go(DM / 128, MT / 128, 1);
    gemm_f16_bias_tanh<1><<<go, 256, GEMM_SMEM>>>(ctx_ptr, bo, nullptr, nullptr, out);
}